// round 1
// baseline (speedup 1.0000x reference)
#include <cuda_runtime.h>

#define DD 64
#define II 64
#define NBATCH 32768
#define TB 128
#define NTHREADS 256

// Scratch (allocation-free rule: __device__ globals)
__device__ float g_C[DD * II * II];   // C[d][i][j] = sum_o W2[d][i][o] * Wg1[d*64+o][j]
__device__ float g_bbp[DD * II];      // per-d bias partial: sum_o b2[d][o]*Wg1[d*64+o][j]

__device__ __forceinline__ float fast_tanh(float v) {
    // tanh(v) = (e^{2v}-1)/(e^{2v}+1); args bounded (~|v|<8) so no overflow.
    float e = __expf(2.0f * v);
    return __fdividef(e - 1.0f, e + 1.0f);
}

// ---------------------------------------------------------------------------
// Kernel A: fold W2[d] @ Wg1[d*64: (d+1)*64, :] -> C[d], plus bias partials.
// grid = 64 (one block per d), 256 threads.
// ---------------------------------------------------------------------------
__global__ __launch_bounds__(NTHREADS) void precompute_C(
    const float* __restrict__ W2,   // [D, I, I]
    const float* __restrict__ Wg1,  // [D*I, I]
    const float* __restrict__ b2)   // [D, I]
{
    __shared__ float W2s[II * II];  // [i][o]
    __shared__ float Wgs[II * II];  // [o][j]
    const int d = blockIdx.x;
    const int tid = threadIdx.x;

    for (int t = tid; t < II * II; t += NTHREADS) {
        W2s[t] = W2[d * II * II + t];
        Wgs[t] = Wg1[d * II * II + t];  // contiguous slice, [o][j]
    }
    __syncthreads();

    for (int t = tid; t < II * II; t += NTHREADS) {
        const int i = t >> 6;
        const int j = t & 63;
        float s = 0.0f;
        #pragma unroll 16
        for (int o = 0; o < II; ++o)
            s = fmaf(W2s[i * II + o], Wgs[o * II + j], s);
        g_C[d * II * II + t] = s;
    }

    if (tid < II) {
        const int j = tid;
        float s = 0.0f;
        #pragma unroll 16
        for (int o = 0; o < II; ++o)
            s = fmaf(b2[d * II + o], Wgs[o * II + j], s);
        g_bbp[d * II + j] = s;
    }
}

// ---------------------------------------------------------------------------
// Kernel B: fused main kernel.
// Per block: 128 batch rows. hg_pre[r][j] = sum_{d,i} tanh(x[r][d]*W1[d][i]+b1[d][i]) * C[d][i][j]
// then out[r] = sum_j tanh(hg_pre[r][j] + bb[j]) * Wg2[j] + bg2.
// grid = 256, 256 threads, 82688 B dynamic smem (2 CTAs/SM).
// ---------------------------------------------------------------------------
__global__ __launch_bounds__(NTHREADS, 2) void kolmo_main(
    const float* __restrict__ x,    // [B, D]
    const float* __restrict__ W1,   // [D, I]
    const float* __restrict__ b1,   // [D, I]
    const float* __restrict__ bg1,  // [I]
    const float* __restrict__ Wg2,  // [I, 1]
    const float* __restrict__ bg2,  // [1]
    float* __restrict__ out)        // [B, 1]
{
    extern __shared__ float smem[];
    float* x_s   = smem;                    // [d][r] padded: 64 * 129
    float* h_s   = x_s + 64 * 129;          // [i][r]: 64 * 128   (16B aligned)
    float* C_s   = h_s + 64 * 128;          // [k][j]: 64 * 64    (16B aligned)
    float* bb_s  = C_s + 64 * 64;           // 64
    float* wg2_s = bb_s + 64;               // 64
    float* red   = C_s;                     // reuse C_s for final reduction

    const int tid = threadIdx.x;
    const int r0  = blockIdx.x * TB;

    // Load x tile transposed: x_s[d][r] = x[r0+r][d]. Coalesced global reads.
    #pragma unroll
    for (int t = tid; t < TB * DD; t += NTHREADS) {
        const int r = t >> 6;
        const int d = t & 63;
        x_s[d * 129 + r] = x[(r0 + r) * DD + d];
    }
    // Folded bias + Wg2 to smem.
    if (tid < II) {
        float s = bg1[tid];
        #pragma unroll 16
        for (int d = 0; d < DD; ++d) s += g_bbp[d * II + tid];
        bb_s[tid]  = s;
        wg2_s[tid] = Wg2[tid];
    }
    __syncthreads();

    const int tr = tid >> 4;  // 0..15 -> rows tr*8 .. tr*8+7
    const int tc = tid & 15;  // 0..15 -> cols tc*4 .. tc*4+3

    float acc[8][4];
    #pragma unroll
    for (int a = 0; a < 8; ++a)
        #pragma unroll
        for (int b = 0; b < 4; ++b) acc[a][b] = 0.0f;

    for (int d = 0; d < DD; ++d) {
        // Stage C[d] (16KB) from global (L2-resident after first wave).
        {
            const float4* Cg = (const float4*)(g_C + d * II * II);
            float4* C4 = (float4*)C_s;
            #pragma unroll
            for (int t = 0; t < 4; ++t) C4[tid + t * NTHREADS] = Cg[tid + t * NTHREADS];
        }
        // Compute h tile transposed: h_s[i][r] = tanh(x[r][d]*W1[d][i]+b1[d][i]).
        #pragma unroll
        for (int t = 0; t < (TB * II) / NTHREADS; ++t) {
            const int idx = tid + t * NTHREADS;
            const int i = idx >> 7;
            const int r = idx & 127;
            const float v = fmaf(x_s[d * 129 + r], __ldg(&W1[d * II + i]), __ldg(&b1[d * II + i]));
            h_s[i * 128 + r] = fast_tanh(v);
        }
        __syncthreads();

        // Register-tiled GEMM: acc += h_s^T(128x64 over k) @ C_s(64x64).
        #pragma unroll 8
        for (int k = 0; k < II; ++k) {
            const float4 a0 = *(const float4*)(h_s + k * 128 + tr * 8);
            const float4 a1 = *(const float4*)(h_s + k * 128 + tr * 8 + 4);
            const float4 bv = *(const float4*)(C_s + k * 64 + tc * 4);
            const float av[8] = {a0.x, a0.y, a0.z, a0.w, a1.x, a1.y, a1.z, a1.w};
            const float bw[4] = {bv.x, bv.y, bv.z, bv.w};
            #pragma unroll
            for (int a = 0; a < 8; ++a)
                #pragma unroll
                for (int b = 0; b < 4; ++b)
                    acc[a][b] = fmaf(av[a], bw[b], acc[a][b]);
        }
        __syncthreads();
    }

    // Epilogue: hg = tanh(hg_pre + bb); partial dot with Wg2; reduce over tc.
    float partial[8];
    #pragma unroll
    for (int a = 0; a < 8; ++a) {
        float s = 0.0f;
        #pragma unroll
        for (int b = 0; b < 4; ++b) {
            const float hg = fast_tanh(acc[a][b] + bb_s[tc * 4 + b]);
            s = fmaf(hg, wg2_s[tc * 4 + b], s);
        }
        partial[a] = s;
    }
    #pragma unroll
    for (int a = 0; a < 8; ++a)
        red[(tr * 8 + a) * 16 + tc] = partial[a];
    __syncthreads();

    if (tid < TB) {
        float s = 0.0f;
        #pragma unroll
        for (int k = 0; k < 16; ++k) s += red[tid * 16 + k];
        out[r0 + tid] = s + bg2[0];
    }
}

// ---------------------------------------------------------------------------
extern "C" void kernel_launch(void* const* d_in, const int* in_sizes, int n_in,
                              void* d_out, int out_size) {
    const float* x   = (const float*)d_in[0];
    const float* W1  = (const float*)d_in[1];
    const float* b1  = (const float*)d_in[2];
    const float* W2  = (const float*)d_in[3];
    const float* b2  = (const float*)d_in[4];
    const float* Wg1 = (const float*)d_in[5];
    const float* bg1 = (const float*)d_in[6];
    const float* Wg2 = (const float*)d_in[7];
    const float* bg2 = (const float*)d_in[8];
    float* out = (float*)d_out;

    const int smem_bytes = (64 * 129 + 64 * 128 + 64 * 64 + 64 + 64) * (int)sizeof(float); // 82688
    cudaFuncSetAttribute(kolmo_main, cudaFuncAttributeMaxDynamicSharedMemorySize, smem_bytes);

    precompute_C<<<DD, NTHREADS>>>(W2, Wg1, b2);
    kolmo_main<<<NBATCH / TB, NTHREADS, smem_bytes>>>(x, W1, b1, bg1, Wg2, bg2, out);
}

// round 3
// speedup vs baseline: 2.1299x; 2.1299x over previous
#include <cuda_runtime.h>
#include <cuda_bf16.h>
#include <cstdint>

#define DD 64
#define II 64
#define NBATCH 32768
#define ROWS 256
#define NTHREADS 256
#define NCTAS (NBATCH / ROWS)      // 128
#define C2LOG2E 2.885390081777927f // 2*log2(e)

// ---- smem map (bytes) ----
#define SM_BB    0        // 64 floats
#define SM_WG2   256      // 64 floats
#define SM_PB    512      // 2 x 128 floats (w,b interleaved)
#define SM_X     1536     // 64*257*4 = 65792
#define SM_A     67584    // 2 bufs x (hi 32768 + lo 32768) = 131072
#define SM_B     198656   // 2 bufs x (hi 8192 + lo 8192)   = 32768
#define SM_TOTAL 231424

// ---- device scratch ----
__device__ uint4 g_Chi4[DD * 512];   // per-d 8KB SW128 bf16 B tile (hi), rows j(64)x128B k-major
__device__ uint4 g_Clo4[DD * 512];
__device__ float g_bbp[DD * II];

__device__ __forceinline__ uint32_t smem_u32(const void* p) {
    uint32_t a;
    asm("{ .reg .u64 t; cvta.to.shared.u64 t, %1; cvt.u32.u64 %0, t; }" : "=r"(a) : "l"(p));
    return a;
}
__device__ __forceinline__ uint32_t swz128(uint32_t off) { return off ^ ((off >> 3) & 0x70); }
__device__ __forceinline__ float ex2f(float x) {
    float r; asm("ex2.approx.ftz.f32 %0, %1;" : "=f"(r) : "f"(x)); return r;
}
// exact tanh given prescaled arg (v' = 2*log2e*v)
__device__ __forceinline__ float tanh_from_p(float vp) {
    float e = ex2f(vp);
    return __fdividef(e - 1.0f, e + 1.0f);
}
__device__ __forceinline__ void ldsm4(uint32_t* r, uint32_t addr) {
    asm volatile("ldmatrix.sync.aligned.m8n8.x4.shared.b16 {%0,%1,%2,%3}, [%4];"
        : "=r"(r[0]), "=r"(r[1]), "=r"(r[2]), "=r"(r[3]) : "r"(addr));
}
__device__ __forceinline__ void mma_bf16(float* c, const uint32_t* a, uint32_t b0, uint32_t b1) {
    asm volatile("mma.sync.aligned.m16n8k16.row.col.f32.bf16.bf16.f32 "
        "{%0,%1,%2,%3}, {%4,%5,%6,%7}, {%8,%9}, {%0,%1,%2,%3};"
        : "+f"(c[0]), "+f"(c[1]), "+f"(c[2]), "+f"(c[3])
        : "r"(a[0]), "r"(a[1]), "r"(a[2]), "r"(a[3]), "r"(b0), "r"(b1));
}

// ---------------------------------------------------------------------------
// Kernel A: fold W2[d] @ Wg1 slice -> C[d]; emit bf16 (hi,lo) SW128 B tiles
// (n-major: byte j*128 + i*2, swizzled) and per-d bias partials.
// ---------------------------------------------------------------------------
__global__ __launch_bounds__(NTHREADS) void precompute_C(
    const float* __restrict__ W2, const float* __restrict__ Wg1,
    const float* __restrict__ b2)
{
    __shared__ float W2s[II * II];
    __shared__ float Wgs[II * II];
    const int d = blockIdx.x;
    const int tid = threadIdx.x;

    for (int t = tid; t < II * II; t += NTHREADS) {
        W2s[t] = W2[d * II * II + t];
        Wgs[t] = Wg1[d * II * II + t];
    }
    __syncthreads();

    __nv_bfloat16* Chi = (__nv_bfloat16*)(g_Chi4 + (size_t)d * 512);
    __nv_bfloat16* Clo = (__nv_bfloat16*)(g_Clo4 + (size_t)d * 512);

    for (int t = tid; t < II * II; t += NTHREADS) {
        const int i = t >> 6;     // K index
        const int j = t & 63;     // N index
        float s = 0.0f;
        #pragma unroll 16
        for (int o = 0; o < II; ++o)
            s = fmaf(W2s[i * II + o], Wgs[o * II + j], s);
        __nv_bfloat16 hi = __float2bfloat16(s);
        __nv_bfloat16 lo = __float2bfloat16(s - __bfloat162float(hi));
        uint32_t off = swz128((uint32_t)(j * 128 + i * 2)) >> 1;
        Chi[off] = hi;
        Clo[off] = lo;
    }

    if (tid < II) {
        const int j = tid;
        float s = 0.0f;
        #pragma unroll 16
        for (int o = 0; o < II; ++o)
            s = fmaf(b2[d * II + o], Wgs[o * II + j], s);
        g_bbp[d * II + j] = s;
    }
}

// ---------------------------------------------------------------------------
// Kernel B: tanh producer + bf16-split mma.sync GEMM + tanh epilogue.
// grid=128, 256 threads (8 warps, 32 rows each), 1 CTA/SM, 231424 B smem.
// ---------------------------------------------------------------------------
__global__ __launch_bounds__(NTHREADS)
void kolmo_mma(
    const float* __restrict__ x,    // [B, 64]
    const float* __restrict__ W1,   // [64, 64]
    const float* __restrict__ b1,   // [64, 64]
    const float* __restrict__ bg1,  // [64]
    const float* __restrict__ Wg2,  // [64, 1]
    const float* __restrict__ bg2,  // [1]
    float* __restrict__ out)        // [B, 1]
{
    extern __shared__ char smem[];
    const uint32_t sb = smem_u32(smem);
    const int tid  = threadIdx.x;
    const int wid  = tid >> 5;
    const int lane = tid & 31;
    const int r0   = blockIdx.x * ROWS;

    float* bb_s  = (float*)(smem + SM_BB);
    float* wg2_s = (float*)(smem + SM_WG2);
    float* pb    = (float*)(smem + SM_PB);
    float* x_s   = (float*)(smem + SM_X);

    // fold bias + Wg2
    if (tid < II) {
        float s = bg1[tid];
        #pragma unroll 16
        for (int d = 0; d < DD; ++d) s += g_bbp[d * II + tid];
        bb_s[tid]  = s;
        wg2_s[tid] = Wg2[tid];
        // params for d=0 (prescaled)
        pb[tid * 2]     = W1[tid] * C2LOG2E;
        pb[tid * 2 + 1] = b1[tid] * C2LOG2E;
    }
    // x tile transposed [d][r], stride 257 (conflict-free both ways)
    for (int idx = tid; idx < ROWS * DD; idx += NTHREADS) {
        const int r = idx >> 6;
        const int d = idx & 63;
        x_s[d * 257 + r] = x[(size_t)(r0 + r) * DD + d];
    }
    // prefetch B(0)
    uint4 bh0 = g_Chi4[tid], bh1 = g_Chi4[tid + 256];
    uint4 bl0 = g_Clo4[tid], bl1 = g_Clo4[tid + 256];
    __syncthreads();

    float acc[64];  // [t(2)][j(8)][q(4)]
    #pragma unroll
    for (int i = 0; i < 64; ++i) acc[i] = 0.0f;

    // per-thread ldmatrix lane geometry
    const uint32_t bRow  = (uint32_t)((lane & 7) + ((lane & 16) ? 8 : 0));  // + p*16
    const uint32_t bKadd = (lane & 8) ? 16u : 0u;
    const uint32_t aRow0 = (uint32_t)(wid * 32 + (lane & 15));
    const uint32_t aKadd = (lane & 16) ? 16u : 0u;
    const uint32_t a_sw  = swz128((uint32_t)(tid * 128));  // producer store base

    #pragma unroll 2
    for (int d = 0; d < DD; ++d) {
        const int buf = d & 1;
        // ---- store B(d) regs -> smem buf ----
        {
            uint4* dh = (uint4*)(smem + SM_B + buf * 16384);
            uint4* dl = (uint4*)(smem + SM_B + buf * 16384 + 8192);
            dh[tid] = bh0; dh[tid + 256] = bh1;
            dl[tid] = bl0; dl[tid + 256] = bl1;
        }
        // ---- prefetch B(d+1) ----
        if (d < DD - 1) {
            const uint4* sh = g_Chi4 + (size_t)(d + 1) * 512;
            const uint4* sl = g_Clo4 + (size_t)(d + 1) * 512;
            bh0 = sh[tid]; bh1 = sh[tid + 256];
            bl0 = sl[tid]; bl1 = sl[tid + 256];
        }
        // ---- stage params(d+1) into other pbuf ----
        if (d < DD - 1 && tid < II) {
            pb[(1 - buf) * 128 + tid * 2]     = W1[(d + 1) * II + tid] * C2LOG2E;
            pb[(1 - buf) * 128 + tid * 2 + 1] = b1[(d + 1) * II + tid] * C2LOG2E;
        }
        // ---- producer: h[row=tid][i] -> bf16 hi/lo into A buf (SW128) ----
        {
            const float xv = x_s[d * 257 + tid];
            const float2* wb2 = (const float2*)(pb + buf * 128);
            char* aH = smem + SM_A + buf * 65536;
            char* aL = aH + 32768;
            #pragma unroll
            for (int c = 0; c < 8; ++c) {
                float h[8];
                #pragma unroll
                for (int u = 0; u < 8; ++u) {
                    const float2 wb = wb2[c * 8 + u];
                    h[u] = tanh_from_p(fmaf(xv, wb.x, wb.y));
                }
                uint32_t hw[4], lw[4];
                #pragma unroll
                for (int q = 0; q < 4; ++q) {
                    const __nv_bfloat16 e0 = __float2bfloat16(h[2 * q]);
                    const __nv_bfloat16 e1 = __float2bfloat16(h[2 * q + 1]);
                    hw[q] = ((uint32_t)__bfloat16_as_ushort(e1) << 16) | __bfloat16_as_ushort(e0);
                    const float l0 = h[2 * q]     - __bfloat162float(e0);
                    const float l1 = h[2 * q + 1] - __bfloat162float(e1);
                    asm("cvt.rn.bf16x2.f32 %0, %1, %2;" : "=r"(lw[q]) : "f"(l1), "f"(l0));
                }
                const uint32_t off = a_sw ^ (uint32_t)(c * 16);
                *(uint4*)(aH + off) = make_uint4(hw[0], hw[1], hw[2], hw[3]);
                *(uint4*)(aL + off) = make_uint4(lw[0], lw[1], lw[2], lw[3]);
            }
        }
        __syncthreads();

        // ---- MMA: acc += Ahi*Bhi + Ahi*Blo + Alo*Bhi ----
        {
            const uint32_t aBase = sb + SM_A + buf * 65536;
            const uint32_t bBase = sb + SM_B + buf * 16384;
            #pragma unroll
            for (int ks = 0; ks < 4; ++ks) {
                const uint32_t kb = (uint32_t)(ks * 32);
                uint32_t bh[16], bl[16];
                #pragma unroll
                for (int p = 0; p < 4; ++p) {
                    const uint32_t v  = (bRow + p * 16) * 128 + kb + bKadd;
                    const uint32_t ad = bBase + swz128(v);
                    ldsm4(bh + p * 4, ad);
                    ldsm4(bl + p * 4, ad + 8192);
                }
                #pragma unroll
                for (int t = 0; t < 2; ++t) {
                    const uint32_t v  = (aRow0 + t * 16) * 128 + kb + aKadd;
                    const uint32_t ad = aBase + swz128(v);
                    uint32_t ah[4], al[4];
                    ldsm4(ah, ad);
                    ldsm4(al, ad + 32768);
                    #pragma unroll
                    for (int j = 0; j < 8; ++j) {
                        float* c = acc + (t * 8 + j) * 4;
                        const int bi = (j >> 1) * 4 + (j & 1) * 2;
                        mma_bf16(c, ah, bh[bi], bh[bi + 1]);
                        mma_bf16(c, ah, bl[bi], bl[bi + 1]);
                        mma_bf16(c, al, bh[bi], bh[bi + 1]);
                    }
                }
            }
        }
    }

    // ---- epilogue: tanh(acc + bb) . Wg2, reduce over lane%4 ----
    {
        const float bg2v = bg2[0];
        float sums[4];
        #pragma unroll
        for (int t = 0; t < 2; ++t) {
            #pragma unroll
            for (int half = 0; half < 2; ++half) {
                float s = 0.0f;
                #pragma unroll
                for (int j = 0; j < 8; ++j) {
                    #pragma unroll
                    for (int qq = 0; qq < 2; ++qq) {
                        const int n = j * 8 + 2 * (lane & 3) + qq;
                        const float v = acc[(t * 8 + j) * 4 + half * 2 + qq] + bb_s[n];
                        s = fmaf(tanh_from_p(v * C2LOG2E), wg2_s[n], s);
                    }
                }
                sums[t * 2 + half] = s;
            }
        }
        #pragma unroll
        for (int k = 0; k < 4; ++k) {
            sums[k] += __shfl_xor_sync(0xFFFFFFFFu, sums[k], 1);
            sums[k] += __shfl_xor_sync(0xFFFFFFFFu, sums[k], 2);
        }
        if ((lane & 3) == 0) {
            const int rbase = r0 + wid * 32 + (lane >> 2);
            out[rbase]      = sums[0] + bg2v;   // t0, rows l/4
            out[rbase + 8]  = sums[1] + bg2v;   // t0, +8
            out[rbase + 16] = sums[2] + bg2v;   // t1
            out[rbase + 24] = sums[3] + bg2v;   // t1, +8
        }
    }
}

// ---------------------------------------------------------------------------
extern "C" void kernel_launch(void* const* d_in, const int* in_sizes, int n_in,
                              void* d_out, int out_size) {
    const float* x   = (const float*)d_in[0];
    const float* W1  = (const float*)d_in[1];
    const float* b1  = (const float*)d_in[2];
    const float* W2  = (const float*)d_in[3];
    const float* b2  = (const float*)d_in[4];
    const float* Wg1 = (const float*)d_in[5];
    const float* bg1 = (const float*)d_in[6];
    const float* Wg2 = (const float*)d_in[7];
    const float* bg2 = (const float*)d_in[8];
    float* out = (float*)d_out;

    cudaFuncSetAttribute(kolmo_mma, cudaFuncAttributeMaxDynamicSharedMemorySize, SM_TOTAL);

    precompute_C<<<DD, NTHREADS>>>(W2, Wg1, b2);
    kolmo_mma<<<NCTAS, NTHREADS, SM_TOTAL>>>(x, W1, b1, bg1, Wg2, bg2, out);
}

// round 4
// speedup vs baseline: 2.2016x; 1.0336x over previous
#include <cuda_runtime.h>
#include <cuda_bf16.h>
#include <cstdint>

#define DD 64
#define II 64
#define NBATCH 32768
#define ROWS 256
#define NTHREADS 384               // 8 consumer warps + 4 producer warps
#define NCTAS (NBATCH / ROWS)      // 128
#define C2LOG2E 2.885390081777927f // 2*log2(e)

// ---- smem map (bytes) ----
#define SM_BB    0        // 64 floats
#define SM_WG2   256      // 64 floats
#define SM_X     512      // 64*257*4 = 65792
#define SM_A     66560    // 2 stages x (hi 32768 + lo 32768) = 131072 (1024-aligned)
#define SM_B     197632   // 2 stages x (hi 8192 + lo 8192)   = 32768  (1024-aligned)
#define SM_TOTAL 230400

// ---- device scratch ----
__device__ uint4  g_Chi4[DD * 512];   // per-d 8KB SW128 bf16 B tile (hi)
__device__ uint4  g_Clo4[DD * 512];   // (lo)
__device__ float  g_bbp[DD * II];
__device__ float2 g_wb[DD * II];      // prescaled (W1*2log2e, b1*2log2e)

__device__ __forceinline__ uint32_t smem_u32(const void* p) {
    uint32_t a;
    asm("{ .reg .u64 t; cvta.to.shared.u64 t, %1; cvt.u32.u64 %0, t; }" : "=r"(a) : "l"(p));
    return a;
}
__device__ __forceinline__ uint32_t swz128(uint32_t off) { return off ^ ((off >> 3) & 0x70); }
__device__ __forceinline__ float ex2f(float x) {
    float r; asm("ex2.approx.ftz.f32 %0, %1;" : "=f"(r) : "f"(x)); return r;
}
// exact tanh given prescaled arg (v' = 2*log2e*v)
__device__ __forceinline__ float tanh_from_p(float vp) {
    float e = ex2f(vp);
    return __fdividef(e - 1.0f, e + 1.0f);
}
__device__ __forceinline__ void ldsm4(uint32_t* r, uint32_t addr) {
    asm volatile("ldmatrix.sync.aligned.m8n8.x4.shared.b16 {%0,%1,%2,%3}, [%4];"
        : "=r"(r[0]), "=r"(r[1]), "=r"(r[2]), "=r"(r[3]) : "r"(addr));
}
__device__ __forceinline__ void mma_bf16(float* c, const uint32_t* a, uint32_t b0, uint32_t b1) {
    asm volatile("mma.sync.aligned.m16n8k16.row.col.f32.bf16.bf16.f32 "
        "{%0,%1,%2,%3}, {%4,%5,%6,%7}, {%8,%9}, {%0,%1,%2,%3};"
        : "+f"(c[0]), "+f"(c[1]), "+f"(c[2]), "+f"(c[3])
        : "r"(a[0]), "r"(a[1]), "r"(a[2]), "r"(a[3]), "r"(b0), "r"(b1));
}

// ---------------------------------------------------------------------------
// Kernel A: fold W2[d] @ Wg1 slice -> C[d] bf16 (hi,lo) SW128 tiles;
// bias partials; prescaled W1/b1.
// ---------------------------------------------------------------------------
__global__ __launch_bounds__(256) void precompute_C(
    const float* __restrict__ W1, const float* __restrict__ b1,
    const float* __restrict__ W2, const float* __restrict__ Wg1,
    const float* __restrict__ b2)
{
    __shared__ float W2s[II * II];
    __shared__ float Wgs[II * II];
    const int d = blockIdx.x;
    const int tid = threadIdx.x;

    for (int t = tid; t < II * II; t += 256) {
        W2s[t] = W2[d * II * II + t];
        Wgs[t] = Wg1[d * II * II + t];
    }
    __syncthreads();

    __nv_bfloat16* Chi = (__nv_bfloat16*)(g_Chi4 + (size_t)d * 512);
    __nv_bfloat16* Clo = (__nv_bfloat16*)(g_Clo4 + (size_t)d * 512);

    for (int t = tid; t < II * II; t += 256) {
        const int i = t >> 6;     // K index
        const int j = t & 63;     // N index
        float s = 0.0f;
        #pragma unroll 16
        for (int o = 0; o < II; ++o)
            s = fmaf(W2s[i * II + o], Wgs[o * II + j], s);
        __nv_bfloat16 hi = __float2bfloat16(s);
        __nv_bfloat16 lo = __float2bfloat16(s - __bfloat162float(hi));
        uint32_t off = swz128((uint32_t)(j * 128 + i * 2)) >> 1;
        Chi[off] = hi;
        Clo[off] = lo;
    }

    if (tid < II) {
        const int j = tid;
        float s = 0.0f;
        #pragma unroll 16
        for (int o = 0; o < II; ++o)
            s = fmaf(b2[d * II + o], Wgs[o * II + j], s);
        g_bbp[d * II + j] = s;
        g_wb[d * II + j] = make_float2(W1[d * II + j] * C2LOG2E,
                                       b1[d * II + j] * C2LOG2E);
    }
}

// ---------------------------------------------------------------------------
// producer helper: one row of h -> bf16 hi/lo packed into A stage
// ---------------------------------------------------------------------------
__device__ __forceinline__ void produce_row(
    float xv, const float2* __restrict__ wb, char* aH, char* aL, uint32_t a_sw)
{
    #pragma unroll
    for (int c = 0; c < 8; ++c) {
        float h[8];
        #pragma unroll
        for (int u = 0; u < 8; ++u) {
            const float2 w = __ldg(&wb[c * 8 + u]);
            h[u] = tanh_from_p(fmaf(xv, w.x, w.y));
        }
        uint32_t hw[4], lw[4];
        #pragma unroll
        for (int q = 0; q < 4; ++q) {
            const __nv_bfloat16 e0 = __float2bfloat16(h[2 * q]);
            const __nv_bfloat16 e1 = __float2bfloat16(h[2 * q + 1]);
            hw[q] = ((uint32_t)__bfloat16_as_ushort(e1) << 16) | __bfloat16_as_ushort(e0);
            const float l0 = h[2 * q]     - __bfloat162float(e0);
            const float l1 = h[2 * q + 1] - __bfloat162float(e1);
            asm("cvt.rn.bf16x2.f32 %0, %1, %2;" : "=r"(lw[q]) : "f"(l1), "f"(l0));
        }
        const uint32_t off = a_sw ^ (uint32_t)(c * 16);
        *(uint4*)(aH + off) = make_uint4(hw[0], hw[1], hw[2], hw[3]);
        *(uint4*)(aL + off) = make_uint4(lw[0], lw[1], lw[2], lw[3]);
    }
}

// ---------------------------------------------------------------------------
// Kernel B: warp-specialized producer/consumer. grid=128, 384 threads.
// warps 0-7: MMA consumers (M=32 each). warps 8-11: tanh producers.
// Ping-pong double buffer, one __syncthreads per d.
// ---------------------------------------------------------------------------
__global__ __launch_bounds__(NTHREADS)
void kolmo_ws(
    const float* __restrict__ x,    // [B, 64]
    const float* __restrict__ bg1,  // [64]
    const float* __restrict__ Wg2,  // [64, 1]
    const float* __restrict__ bg2,  // [1]
    float* __restrict__ out)        // [B, 1]
{
    extern __shared__ char smem[];
    const uint32_t sb = smem_u32(smem);
    const int tid  = threadIdx.x;
    const int wid  = tid >> 5;
    const int lane = tid & 31;
    const int r0   = blockIdx.x * ROWS;

    float* bb_s  = (float*)(smem + SM_BB);
    float* wg2_s = (float*)(smem + SM_WG2);
    float* x_s   = (float*)(smem + SM_X);

    // prologue: bias fold + Wg2 (threads 0-63, all consumers)
    if (tid < II) {
        float s = bg1[tid];
        #pragma unroll 16
        for (int d = 0; d < DD; ++d) s += g_bbp[d * II + tid];
        bb_s[tid]  = s;
        wg2_s[tid] = Wg2[tid];
    }
    // x tile transposed [d][r], stride 257 (conflict-free)
    for (int idx = tid; idx < ROWS * DD; idx += NTHREADS) {
        const int r = idx >> 6;
        const int d = idx & 63;
        x_s[d * 257 + r] = x[(size_t)(r0 + r) * DD + d];
    }
    __syncthreads();

    if (wid >= 8) {
        // ================= PRODUCER warps (8-11), 128 threads =================
        const int ptid = tid - 256;  // 0..127
        const uint32_t a_sw0 = swz128((uint32_t)(ptid * 128));
        const uint32_t a_sw1 = swz128((uint32_t)((ptid + 128) * 128));

        // produce stage 0 (d=0)
        {
            uint4* dh = (uint4*)(smem + SM_B);
            uint4* dl = (uint4*)(smem + SM_B + 8192);
            #pragma unroll
            for (int k = 0; k < 4; ++k) { dh[ptid + k * 128] = g_Chi4[ptid + k * 128];
                                          dl[ptid + k * 128] = g_Clo4[ptid + k * 128]; }
            char* aH = smem + SM_A;
            char* aL = aH + 32768;
            const float2* wb = g_wb;
            produce_row(x_s[ptid],       wb, aH, aL, a_sw0);
            produce_row(x_s[ptid + 128], wb, aH, aL, a_sw1);
        }
        __syncthreads();

        for (int d = 0; d < DD; ++d) {
            const int dn = d + 1;
            if (dn < DD) {
                const int s = dn & 1;
                uint4* dh = (uint4*)(smem + SM_B + s * 16384);
                uint4* dl = (uint4*)(smem + SM_B + s * 16384 + 8192);
                const uint4* sh = g_Chi4 + (size_t)dn * 512;
                const uint4* sl = g_Clo4 + (size_t)dn * 512;
                #pragma unroll
                for (int k = 0; k < 4; ++k) { dh[ptid + k * 128] = sh[ptid + k * 128];
                                              dl[ptid + k * 128] = sl[ptid + k * 128]; }
                char* aH = smem + SM_A + s * 65536;
                char* aL = aH + 32768;
                const float2* wb = g_wb + dn * II;
                produce_row(x_s[dn * 257 + ptid],       wb, aH, aL, a_sw0);
                produce_row(x_s[dn * 257 + ptid + 128], wb, aH, aL, a_sw1);
            }
            __syncthreads();
        }
        // producers done (no epilogue)
    } else {
        // ================= CONSUMER warps (0-7), 256 threads ==================
        float acc[64];  // [t(2)][j(8)][q(4)]
        #pragma unroll
        for (int i = 0; i < 64; ++i) acc[i] = 0.0f;

        const uint32_t bRow  = (uint32_t)((lane & 7) + ((lane & 16) ? 8 : 0));
        const uint32_t bKadd = (lane & 8) ? 16u : 0u;
        const uint32_t aRow0 = (uint32_t)(wid * 32 + (lane & 15));
        const uint32_t aKadd = (lane & 16) ? 16u : 0u;

        __syncthreads();  // matches producers' stage-0 sync

        for (int d = 0; d < DD; ++d) {
            const int s = d & 1;
            const uint32_t aBase = sb + SM_A + s * 65536;
            const uint32_t bBase = sb + SM_B + s * 16384;
            #pragma unroll
            for (int ks = 0; ks < 4; ++ks) {
                const uint32_t kb = (uint32_t)(ks * 32);
                uint32_t bh[16], bl[16];
                #pragma unroll
                for (int p = 0; p < 4; ++p) {
                    const uint32_t v  = (bRow + p * 16) * 128 + kb + bKadd;
                    const uint32_t ad = bBase + swz128(v);
                    ldsm4(bh + p * 4, ad);
                    ldsm4(bl + p * 4, ad + 8192);
                }
                #pragma unroll
                for (int t = 0; t < 2; ++t) {
                    const uint32_t v  = (aRow0 + t * 16) * 128 + kb + aKadd;
                    const uint32_t ad = aBase + swz128(v);
                    uint32_t ah[4], al[4];
                    ldsm4(ah, ad);
                    ldsm4(al, ad + 32768);
                    #pragma unroll
                    for (int j = 0; j < 8; ++j) {
                        float* c = acc + (t * 8 + j) * 4;
                        const int bi = (j >> 1) * 4 + (j & 1) * 2;
                        mma_bf16(c, ah, bh[bi], bh[bi + 1]);
                        mma_bf16(c, ah, bl[bi], bl[bi + 1]);
                        mma_bf16(c, al, bh[bi], bh[bi + 1]);
                    }
                }
            }
            __syncthreads();
        }

        // ---- epilogue: tanh(acc + bb) . Wg2, reduce over lane%4 ----
        const float bg2v = bg2[0];
        float sums[4];
        #pragma unroll
        for (int t = 0; t < 2; ++t) {
            #pragma unroll
            for (int half = 0; half < 2; ++half) {
                float s = 0.0f;
                #pragma unroll
                for (int j = 0; j < 8; ++j) {
                    #pragma unroll
                    for (int qq = 0; qq < 2; ++qq) {
                        const int n = j * 8 + 2 * (lane & 3) + qq;
                        const float v = acc[(t * 8 + j) * 4 + half * 2 + qq] + bb_s[n];
                        s = fmaf(tanh_from_p(v * C2LOG2E), wg2_s[n], s);
                    }
                }
                sums[t * 2 + half] = s;
            }
        }
        #pragma unroll
        for (int k = 0; k < 4; ++k) {
            sums[k] += __shfl_xor_sync(0xFFFFFFFFu, sums[k], 1);
            sums[k] += __shfl_xor_sync(0xFFFFFFFFu, sums[k], 2);
        }
        if ((lane & 3) == 0) {
            const int rbase = r0 + wid * 32 + (lane >> 2);
            out[rbase]      = sums[0] + bg2v;
            out[rbase + 8]  = sums[1] + bg2v;
            out[rbase + 16] = sums[2] + bg2v;
            out[rbase + 24] = sums[3] + bg2v;
        }
    }
}

// ---------------------------------------------------------------------------
extern "C" void kernel_launch(void* const* d_in, const int* in_sizes, int n_in,
                              void* d_out, int out_size) {
    const float* x   = (const float*)d_in[0];
    const float* W1  = (const float*)d_in[1];
    const float* b1  = (const float*)d_in[2];
    const float* W2  = (const float*)d_in[3];
    const float* b2  = (const float*)d_in[4];
    const float* Wg1 = (const float*)d_in[5];
    const float* bg1 = (const float*)d_in[6];
    const float* Wg2 = (const float*)d_in[7];
    const float* bg2 = (const float*)d_in[8];
    float* out = (float*)d_out;

    cudaFuncSetAttribute(kolmo_ws, cudaFuncAttributeMaxDynamicSharedMemorySize, SM_TOTAL);

    precompute_C<<<DD, 256>>>(W1, b1, W2, Wg1, b2);
    kolmo_ws<<<NCTAS, NTHREADS, SM_TOTAL>>>(x, bg1, Wg2, bg2, out);
}

// round 5
// speedup vs baseline: 2.7051x; 1.2287x over previous
#include <cuda_runtime.h>
#include <cuda_bf16.h>
#include <cstdint>

#define DD 64
#define II 64
#define NBATCH 32768
#define ROWS 128
#define NTHREADS 256
#define NCTAS (NBATCH / ROWS)      // 256
#define C2LOG2E 2.885390081777927f // 2*log2(e)

// ---- smem map (per CTA) ----
#define SM_BB      0       // 64 floats
#define SM_WG2     256     // 64 floats
#define SM_STG     1024    // 2 stages: [hi 8192 | lo 8192 | wb 512 | pad 512]
#define STG_STRIDE 17408
#define SM_TOTAL   (1024 + 2 * STG_STRIDE)   // 35840

// ---- device scratch ----
__device__ uint4  g_Chi4[DD * 512];   // per-d 8KB SW128 bf16 B tile (hi)
__device__ uint4  g_Clo4[DD * 512];   // (lo)
__device__ float  g_bbp[DD * II];
__device__ float2 g_wb[DD * II];      // prescaled (W1*2log2e, b1*2log2e)
__device__ float  g_xT[(size_t)DD * NBATCH];  // 8MB transposed x

__device__ __forceinline__ uint32_t smem_u32(const void* p) {
    uint32_t a;
    asm("{ .reg .u64 t; cvta.to.shared.u64 t, %1; cvt.u32.u64 %0, t; }" : "=r"(a) : "l"(p));
    return a;
}
__device__ __forceinline__ uint32_t swz128(uint32_t off) { return off ^ ((off >> 3) & 0x70); }
__device__ __forceinline__ float ex2f(float x) {
    float r; asm("ex2.approx.ftz.f32 %0, %1;" : "=f"(r) : "f"(x)); return r;
}
// exact tanh given prescaled arg (v' = 2*log2e*v)
__device__ __forceinline__ float tanh_from_p(float vp) {
    float e = ex2f(vp);
    return __fdividef(e - 1.0f, e + 1.0f);
}
__device__ __forceinline__ void ldsm4(uint32_t* r, uint32_t addr) {
    asm volatile("ldmatrix.sync.aligned.m8n8.x4.shared.b16 {%0,%1,%2,%3}, [%4];"
        : "=r"(r[0]), "=r"(r[1]), "=r"(r[2]), "=r"(r[3]) : "r"(addr));
}
__device__ __forceinline__ void mma_bf16(float* c, const uint32_t* a, uint32_t b0, uint32_t b1) {
    asm volatile("mma.sync.aligned.m16n8k16.row.col.f32.bf16.bf16.f32 "
        "{%0,%1,%2,%3}, {%4,%5,%6,%7}, {%8,%9}, {%0,%1,%2,%3};"
        : "+f"(c[0]), "+f"(c[1]), "+f"(c[2]), "+f"(c[3])
        : "r"(a[0]), "r"(a[1]), "r"(a[2]), "r"(a[3]), "r"(b0), "r"(b1));
}
__device__ __forceinline__ void cp16(uint32_t saddr, const void* gptr) {
    asm volatile("cp.async.cg.shared.global [%0], [%1], 16;" :: "r"(saddr), "l"(gptr) : "memory");
}
#define CP_COMMIT() asm volatile("cp.async.commit_group;" ::: "memory")
#define CP_WAIT0()  asm volatile("cp.async.wait_group 0;" ::: "memory")

// bf16 hi/lo split pack of a float pair
__device__ __forceinline__ void pack2(float a, float b, uint32_t& hi, uint32_t& lo) {
    const __nv_bfloat16 e0 = __float2bfloat16(a);
    const __nv_bfloat16 e1 = __float2bfloat16(b);
    hi = ((uint32_t)__bfloat16_as_ushort(e1) << 16) | __bfloat16_as_ushort(e0);
    const float l0 = a - __bfloat162float(e0);
    const float l1 = b - __bfloat162float(e1);
    asm("cvt.rn.bf16x2.f32 %0, %1, %2;" : "=r"(lo) : "f"(l1), "f"(l0));
}

// ---------------------------------------------------------------------------
// Kernel T: transpose x [B,64] -> g_xT [64,B]
// ---------------------------------------------------------------------------
__global__ __launch_bounds__(256) void transpose_x(const float* __restrict__ x) {
    __shared__ float tile[64][65];
    const int rb = blockIdx.x * 64;
    for (int i = threadIdx.x; i < 64 * 64; i += 256) {
        const int r = i >> 6, c = i & 63;
        tile[r][c] = x[(size_t)(rb + r) * 64 + c];
    }
    __syncthreads();
    for (int i = threadIdx.x; i < 64 * 64; i += 256) {
        const int c = i >> 6, r = i & 63;
        g_xT[(size_t)c * NBATCH + rb + r] = tile[r][c];
    }
}

// ---------------------------------------------------------------------------
// Kernel A: fold W2[d] @ Wg1 slice -> C[d] bf16 (hi,lo) SW128 tiles;
// bias partials; prescaled W1/b1.
// ---------------------------------------------------------------------------
__global__ __launch_bounds__(256) void precompute_C(
    const float* __restrict__ W1, const float* __restrict__ b1,
    const float* __restrict__ W2, const float* __restrict__ Wg1,
    const float* __restrict__ b2)
{
    __shared__ float W2s[II * II];
    __shared__ float Wgs[II * II];
    const int d = blockIdx.x;
    const int tid = threadIdx.x;

    for (int t = tid; t < II * II; t += 256) {
        W2s[t] = W2[d * II * II + t];
        Wgs[t] = Wg1[d * II * II + t];
    }
    __syncthreads();

    __nv_bfloat16* Chi = (__nv_bfloat16*)(g_Chi4 + (size_t)d * 512);
    __nv_bfloat16* Clo = (__nv_bfloat16*)(g_Clo4 + (size_t)d * 512);

    for (int t = tid; t < II * II; t += 256) {
        const int i = t >> 6;     // K index
        const int j = t & 63;     // N index
        float s = 0.0f;
        #pragma unroll 16
        for (int o = 0; o < II; ++o)
            s = fmaf(W2s[i * II + o], Wgs[o * II + j], s);
        __nv_bfloat16 hi = __float2bfloat16(s);
        __nv_bfloat16 lo = __float2bfloat16(s - __bfloat162float(hi));
        uint32_t off = swz128((uint32_t)(j * 128 + i * 2)) >> 1;
        Chi[off] = hi;
        Clo[off] = lo;
    }

    if (tid < II) {
        const int j = tid;
        float s = 0.0f;
        #pragma unroll 16
        for (int o = 0; o < II; ++o)
            s = fmaf(b2[d * II + o], Wgs[o * II + j], s);
        g_bbp[d * II + j] = s;
        g_wb[d * II + j] = make_float2(W1[d * II + j] * C2LOG2E,
                                       b1[d * II + j] * C2LOG2E);
    }
}

// ---------------------------------------------------------------------------
// Kernel B: in-register A fragments (tanh on the fly), cp.async B pipeline.
// grid=256, 256 threads (8 warps, M=16 each), 2 CTAs/SM.
// ---------------------------------------------------------------------------
__global__ __launch_bounds__(NTHREADS, 2)
void kolmo_v5(
    const float* __restrict__ bg1,  // [64]
    const float* __restrict__ Wg2,  // [64, 1]
    const float* __restrict__ bg2,  // [1]
    float* __restrict__ out)        // [B, 1]
{
    extern __shared__ char smem[];
    const uint32_t sb = smem_u32(smem);
    const int tid  = threadIdx.x;
    const int wid  = tid >> 5;
    const int lane = tid & 31;
    const int r0   = blockIdx.x * ROWS;

    float* bb_s  = (float*)(smem + SM_BB);
    float* wg2_s = (float*)(smem + SM_WG2);

    if (tid < II) {
        float s = bg1[tid];
        #pragma unroll 16
        for (int d = 0; d < DD; ++d) s += g_bbp[d * II + tid];
        bb_s[tid]  = s;
        wg2_s[tid] = Wg2[tid];
    }

    // issue B stage 0 (hi, lo, wb) via cp.async
    {
        const uint32_t st = sb + SM_STG;
        cp16(st          + tid * 16, g_Chi4 + tid);
        cp16(st +  4096  + tid * 16, g_Chi4 + 256 + tid);
        cp16(st +  8192  + tid * 16, g_Clo4 + tid);
        cp16(st + 12288  + tid * 16, g_Clo4 + 256 + tid);
        if (tid < 32) cp16(st + 16384 + tid * 16, (const char*)g_wb + tid * 16);
        CP_COMMIT();
    }

    // lane geometry
    const uint32_t bRow  = (uint32_t)((lane & 7) + ((lane & 16) ? 8 : 0));
    const uint32_t bKadd = (lane & 8) ? 16u : 0u;
    const int  mrow = wid * 16 + (lane >> 2);        // CTA-local row (and +8)
    const int  kc   = 2 * (lane & 3);
    const float* xg = g_xT + r0 + mrow;              // + d*NBATCH

    float acc[32];
    #pragma unroll
    for (int i = 0; i < 32; ++i) acc[i] = 0.0f;

    for (int d = 0; d < DD; ++d) {
        CP_WAIT0();
        __syncthreads();
        const int s = d & 1;
        const uint32_t stg = sb + SM_STG + s * STG_STRIDE;

        // issue next stage into the other buffer (safe: everyone synced)
        if (d + 1 < DD) {
            const uint32_t st = sb + SM_STG + (1 - s) * STG_STRIDE;
            const uint4* sh = g_Chi4 + (size_t)(d + 1) * 512;
            const uint4* sl = g_Clo4 + (size_t)(d + 1) * 512;
            cp16(st          + tid * 16, sh + tid);
            cp16(st +  4096  + tid * 16, sh + 256 + tid);
            cp16(st +  8192  + tid * 16, sl + tid);
            cp16(st + 12288  + tid * 16, sl + 256 + tid);
            if (tid < 32) cp16(st + 16384 + tid * 16,
                               (const char*)(g_wb + (size_t)(d + 1) * II) + tid * 16);
            CP_COMMIT();
        }

        const float xv0 = __ldg(&xg[(size_t)d * NBATCH]);
        const float xv1 = __ldg(&xg[(size_t)d * NBATCH + 8]);
        const float2* wb_s = (const float2*)(smem + SM_STG + s * STG_STRIDE + 16384);

        #pragma unroll
        for (int ks = 0; ks < 4; ++ks) {
            // B fragments (hi + lo)
            uint32_t bh[16], bl[16];
            const uint32_t kb = (uint32_t)(ks * 32);
            #pragma unroll
            for (int p = 0; p < 4; ++p) {
                const uint32_t v  = (bRow + p * 16) * 128 + kb + bKadd;
                const uint32_t ad = stg + swz128(v);
                ldsm4(bh + p * 4, ad);
                ldsm4(bl + p * 4, ad + 8192);
            }
            // A fragment: 8 tanh in-lane
            const int k0 = ks * 16 + kc;
            const float2 w0 = wb_s[k0],     w1 = wb_s[k0 + 1];
            const float2 w8 = wb_s[k0 + 8], w9 = wb_s[k0 + 9];
            const float h00 = tanh_from_p(fmaf(xv0, w0.x, w0.y));
            const float h01 = tanh_from_p(fmaf(xv0, w1.x, w1.y));
            const float h10 = tanh_from_p(fmaf(xv1, w0.x, w0.y));
            const float h11 = tanh_from_p(fmaf(xv1, w1.x, w1.y));
            const float h08 = tanh_from_p(fmaf(xv0, w8.x, w8.y));
            const float h09 = tanh_from_p(fmaf(xv0, w9.x, w9.y));
            const float h18 = tanh_from_p(fmaf(xv1, w8.x, w8.y));
            const float h19 = tanh_from_p(fmaf(xv1, w9.x, w9.y));
            uint32_t ah[4], al[4];
            pack2(h00, h01, ah[0], al[0]);
            pack2(h10, h11, ah[1], al[1]);
            pack2(h08, h09, ah[2], al[2]);
            pack2(h18, h19, ah[3], al[3]);

            #pragma unroll
            for (int j = 0; j < 8; ++j) {
                float* c = acc + j * 4;
                const int bi = (j >> 1) * 4 + (j & 1) * 2;
                mma_bf16(c, ah, bh[bi], bh[bi + 1]);
                mma_bf16(c, ah, bl[bi], bl[bi + 1]);
                mma_bf16(c, al, bh[bi], bh[bi + 1]);
            }
        }
    }

    // ---- epilogue: tanh(acc + bb) . Wg2, reduce over lane&3 ----
    {
        const float bg2v = bg2[0];
        float s0 = 0.0f, s1 = 0.0f;
        #pragma unroll
        for (int j = 0; j < 8; ++j) {
            #pragma unroll
            for (int q = 0; q < 2; ++q) {
                const int n = j * 8 + kc + q;
                const float bbv = bb_s[n], wgv = wg2_s[n];
                s0 = fmaf(tanh_from_p((acc[j * 4 + q]     + bbv) * C2LOG2E), wgv, s0);
                s1 = fmaf(tanh_from_p((acc[j * 4 + 2 + q] + bbv) * C2LOG2E), wgv, s1);
            }
        }
        s0 += __shfl_xor_sync(0xFFFFFFFFu, s0, 1);
        s0 += __shfl_xor_sync(0xFFFFFFFFu, s0, 2);
        s1 += __shfl_xor_sync(0xFFFFFFFFu, s1, 1);
        s1 += __shfl_xor_sync(0xFFFFFFFFu, s1, 2);
        if ((lane & 3) == 0) {
            out[r0 + mrow]     = s0 + bg2v;
            out[r0 + mrow + 8] = s1 + bg2v;
        }
    }
}

// ---------------------------------------------------------------------------
extern "C" void kernel_launch(void* const* d_in, const int* in_sizes, int n_in,
                              void* d_out, int out_size) {
    const float* x   = (const float*)d_in[0];
    const float* W1  = (const float*)d_in[1];
    const float* b1  = (const float*)d_in[2];
    const float* W2  = (const float*)d_in[3];
    const float* b2  = (const float*)d_in[4];
    const float* Wg1 = (const float*)d_in[5];
    const float* bg1 = (const float*)d_in[6];
    const float* Wg2 = (const float*)d_in[7];
    const float* bg2 = (const float*)d_in[8];
    float* out = (float*)d_out;

    cudaFuncSetAttribute(kolmo_v5, cudaFuncAttributeMaxDynamicSharedMemorySize, SM_TOTAL);

    transpose_x<<<NBATCH / 64, 256>>>(x);
    precompute_C<<<DD, 256>>>(W1, b1, W2, Wg1, b2);
    kolmo_v5<<<NCTAS, NTHREADS, SM_TOTAL>>>(bg1, Wg2, bg2, out);
}

// round 6
// speedup vs baseline: 3.8374x; 1.4186x over previous
#include <cuda_runtime.h>
#include <cuda_fp16.h>
#include <cstdint>

#define DD 64
#define II 64
#define NBATCH 32768
#define ROWS 128
#define NTHREADS 256
#define NCTAS (NBATCH / ROWS)      // 256
#define C2LOG2E 2.885390081777927f // 2*log2(e)

// ---- smem map (per CTA) ----
#define SM_BB      0       // 64 floats
#define SM_WG2     256     // 64 floats
#define SM_STG     1024    // 2 stages: [hi 8192 | lo 8192 | wb 512 | pad 512]
#define STG_STRIDE 17408
#define SM_TOTAL   (1024 + 2 * STG_STRIDE)   // 35840

// ---- device scratch ----
__device__ uint4  g_Chi4[DD * 512];   // per-d 8KB SW128 fp16 B tile (hi)
__device__ uint4  g_Clo4[DD * 512];   // (lo)
__device__ float  g_bbp[DD * II];
__device__ float2 g_wb[DD * II];      // prescaled (W1*2log2e, b1*2log2e)

__device__ __forceinline__ uint32_t smem_u32(const void* p) {
    uint32_t a;
    asm("{ .reg .u64 t; cvta.to.shared.u64 t, %1; cvt.u32.u64 %0, t; }" : "=r"(a) : "l"(p));
    return a;
}
__device__ __forceinline__ uint32_t swz128(uint32_t off) { return off ^ ((off >> 3) & 0x70); }
__device__ __forceinline__ float ex2f(float x) {
    float r; asm("ex2.approx.ftz.f32 %0, %1;" : "=f"(r) : "f"(x)); return r;
}
// exact tanh given prescaled arg (v' = 2*log2e*v)
__device__ __forceinline__ float tanh_from_p(float vp) {
    float e = ex2f(vp);
    return __fdividef(e - 1.0f, e + 1.0f);
}
__device__ __forceinline__ void ldsm4(uint32_t* r, uint32_t addr) {
    asm volatile("ldmatrix.sync.aligned.m8n8.x4.shared.b16 {%0,%1,%2,%3}, [%4];"
        : "=r"(r[0]), "=r"(r[1]), "=r"(r[2]), "=r"(r[3]) : "r"(addr));
}
__device__ __forceinline__ void mma_fp16(float* c, const uint32_t* a, uint32_t b0, uint32_t b1) {
    asm volatile("mma.sync.aligned.m16n8k16.row.col.f32.f16.f16.f32 "
        "{%0,%1,%2,%3}, {%4,%5,%6,%7}, {%8,%9}, {%0,%1,%2,%3};"
        : "+f"(c[0]), "+f"(c[1]), "+f"(c[2]), "+f"(c[3])
        : "r"(a[0]), "r"(a[1]), "r"(a[2]), "r"(a[3]), "r"(b0), "r"(b1));
}
__device__ __forceinline__ void cp16(uint32_t saddr, const void* gptr) {
    asm volatile("cp.async.cg.shared.global [%0], [%1], 16;" :: "r"(saddr), "l"(gptr) : "memory");
}
#define CP_COMMIT() asm volatile("cp.async.commit_group;" ::: "memory")
#define CP_WAIT0()  asm volatile("cp.async.wait_group 0;" ::: "memory")

// pack float pair -> fp16x2 (b in high half)
__device__ __forceinline__ uint32_t packh2(float a, float b) {
    uint32_t r;
    asm("cvt.rn.f16x2.f32 %0, %1, %2;" : "=r"(r) : "f"(b), "f"(a));
    return r;
}

// ---------------------------------------------------------------------------
// Kernel A: fold W2[d] @ Wg1 slice -> C[d] fp16 (hi,lo) SW128 tiles;
// bias partials; prescaled W1/b1.
// ---------------------------------------------------------------------------
__global__ __launch_bounds__(256) void precompute_C(
    const float* __restrict__ W1, const float* __restrict__ b1,
    const float* __restrict__ W2, const float* __restrict__ Wg1,
    const float* __restrict__ b2)
{
    __shared__ float W2s[II * II];
    __shared__ float Wgs[II * II];
    const int d = blockIdx.x;
    const int tid = threadIdx.x;

    for (int t = tid; t < II * II; t += 256) {
        W2s[t] = W2[d * II * II + t];
        Wgs[t] = Wg1[d * II * II + t];
    }
    __syncthreads();

    __half* Chi = (__half*)(g_Chi4 + (size_t)d * 512);
    __half* Clo = (__half*)(g_Clo4 + (size_t)d * 512);

    for (int t = tid; t < II * II; t += 256) {
        const int i = t >> 6;     // K index
        const int j = t & 63;     // N index
        float s = 0.0f;
        #pragma unroll 16
        for (int o = 0; o < II; ++o)
            s = fmaf(W2s[i * II + o], Wgs[o * II + j], s);
        const __half hi = __float2half_rn(s);
        const __half lo = __float2half_rn(s - __half2float(hi));
        uint32_t off = swz128((uint32_t)(j * 128 + i * 2)) >> 1;
        Chi[off] = hi;
        Clo[off] = lo;
    }

    if (tid < II) {
        const int j = tid;
        float s = 0.0f;
        #pragma unroll 16
        for (int o = 0; o < II; ++o)
            s = fmaf(b2[d * II + o], Wgs[o * II + j], s);
        g_bbp[d * II + j] = s;
        g_wb[d * II + j] = make_float2(W1[d * II + j] * C2LOG2E,
                                       b1[d * II + j] * C2LOG2E);
    }
}

// ---------------------------------------------------------------------------
// Kernel B: fp16 A in-register (tanh on the fly), B fp16 hi/lo via cp.async.
// 2 MMAs per output tile. grid=256, 256 threads, 2 CTAs/SM.
// ---------------------------------------------------------------------------
__global__ __launch_bounds__(NTHREADS, 2)
void kolmo_v6(
    const float* __restrict__ x,    // [B, 64]
    const float* __restrict__ bg1,  // [64]
    const float* __restrict__ Wg2,  // [64, 1]
    const float* __restrict__ bg2,  // [1]
    float* __restrict__ out)        // [B, 1]
{
    extern __shared__ char smem[];
    const uint32_t sb = smem_u32(smem);
    const int tid  = threadIdx.x;
    const int wid  = tid >> 5;
    const int lane = tid & 31;
    const int r0   = blockIdx.x * ROWS;

    float* bb_s  = (float*)(smem + SM_BB);
    float* wg2_s = (float*)(smem + SM_WG2);

    if (tid < II) {
        float s = bg1[tid];
        #pragma unroll 16
        for (int d = 0; d < DD; ++d) s += g_bbp[d * II + tid];
        bb_s[tid]  = s;
        wg2_s[tid] = Wg2[tid];
    }

    // issue B stage 0 (hi, lo, wb) via cp.async
    {
        const uint32_t st = sb + SM_STG;
        cp16(st          + tid * 16, g_Chi4 + tid);
        cp16(st +  4096  + tid * 16, g_Chi4 + 256 + tid);
        cp16(st +  8192  + tid * 16, g_Clo4 + tid);
        cp16(st + 12288  + tid * 16, g_Clo4 + 256 + tid);
        if (tid < 32) cp16(st + 16384 + tid * 16, (const char*)g_wb + tid * 16);
        CP_COMMIT();
    }

    // lane geometry
    const uint32_t bRow  = (uint32_t)((lane & 7) + ((lane & 16) ? 8 : 0));
    const uint32_t bKadd = (lane & 8) ? 16u : 0u;
    const int  mrow = wid * 16 + (lane >> 2);        // CTA-local row (and +8)
    const int  kc   = 2 * (lane & 3);
    const float* xr0 = x + (size_t)(r0 + mrow) * 64;      // row, walk d
    const float* xr1 = x + (size_t)(r0 + mrow + 8) * 64;

    float acc[32];
    #pragma unroll
    for (int i = 0; i < 32; ++i) acc[i] = 0.0f;

    for (int d = 0; d < DD; ++d) {
        CP_WAIT0();
        __syncthreads();
        const int s = d & 1;
        const uint32_t stg = sb + SM_STG + s * STG_STRIDE;

        // issue next stage into the other buffer
        if (d + 1 < DD) {
            const uint32_t st = sb + SM_STG + (1 - s) * STG_STRIDE;
            const uint4* sh = g_Chi4 + (size_t)(d + 1) * 512;
            const uint4* sl = g_Clo4 + (size_t)(d + 1) * 512;
            cp16(st          + tid * 16, sh + tid);
            cp16(st +  4096  + tid * 16, sh + 256 + tid);
            cp16(st +  8192  + tid * 16, sl + tid);
            cp16(st + 12288  + tid * 16, sl + 256 + tid);
            if (tid < 32) cp16(st + 16384 + tid * 16,
                               (const char*)(g_wb + (size_t)(d + 1) * II) + tid * 16);
            CP_COMMIT();
        }

        const float xv0 = __ldg(xr0 + d);
        const float xv1 = __ldg(xr1 + d);
        const float2* wb_s = (const float2*)(smem + SM_STG + s * STG_STRIDE + 16384);

        #pragma unroll
        for (int ks = 0; ks < 4; ++ks) {
            // B fragments (hi + lo)
            uint32_t bh[16], bl[16];
            const uint32_t kb = (uint32_t)(ks * 32);
            #pragma unroll
            for (int p = 0; p < 4; ++p) {
                const uint32_t v  = (bRow + p * 16) * 128 + kb + bKadd;
                const uint32_t ad = stg + swz128(v);
                ldsm4(bh + p * 4, ad);
                ldsm4(bl + p * 4, ad + 8192);
            }
            // A fragment: 8 tanh in-lane -> fp16
            const int k0 = ks * 16 + kc;
            const float2 w0 = wb_s[k0],     w1 = wb_s[k0 + 1];
            const float2 w8 = wb_s[k0 + 8], w9 = wb_s[k0 + 9];
            uint32_t ah[4];
            ah[0] = packh2(tanh_from_p(fmaf(xv0, w0.x, w0.y)),
                           tanh_from_p(fmaf(xv0, w1.x, w1.y)));
            ah[1] = packh2(tanh_from_p(fmaf(xv1, w0.x, w0.y)),
                           tanh_from_p(fmaf(xv1, w1.x, w1.y)));
            ah[2] = packh2(tanh_from_p(fmaf(xv0, w8.x, w8.y)),
                           tanh_from_p(fmaf(xv0, w9.x, w9.y)));
            ah[3] = packh2(tanh_from_p(fmaf(xv1, w8.x, w8.y)),
                           tanh_from_p(fmaf(xv1, w9.x, w9.y)));

            #pragma unroll
            for (int j = 0; j < 8; ++j) {
                float* c = acc + j * 4;
                const int bi = (j >> 1) * 4 + (j & 1) * 2;
                mma_fp16(c, ah, bh[bi], bh[bi + 1]);
                mma_fp16(c, ah, bl[bi], bl[bi + 1]);
            }
        }
    }

    // ---- epilogue: tanh(acc + bb) . Wg2, reduce over lane&3 ----
    {
        const float bg2v = bg2[0];
        float s0 = 0.0f, s1 = 0.0f;
        #pragma unroll
        for (int j = 0; j < 8; ++j) {
            #pragma unroll
            for (int q = 0; q < 2; ++q) {
                const int n = j * 8 + kc + q;
                const float bbv = bb_s[n], wgv = wg2_s[n];
                s0 = fmaf(tanh_from_p((acc[j * 4 + q]     + bbv) * C2LOG2E), wgv, s0);
                s1 = fmaf(tanh_from_p((acc[j * 4 + 2 + q] + bbv) * C2LOG2E), wgv, s1);
            }
        }
        s0 += __shfl_xor_sync(0xFFFFFFFFu, s0, 1);
        s0 += __shfl_xor_sync(0xFFFFFFFFu, s0, 2);
        s1 += __shfl_xor_sync(0xFFFFFFFFu, s1, 1);
        s1 += __shfl_xor_sync(0xFFFFFFFFu, s1, 2);
        if ((lane & 3) == 0) {
            out[r0 + mrow]     = s0 + bg2v;
            out[r0 + mrow + 8] = s1 + bg2v;
        }
    }
}

// ---------------------------------------------------------------------------
extern "C" void kernel_launch(void* const* d_in, const int* in_sizes, int n_in,
                              void* d_out, int out_size) {
    const float* x   = (const float*)d_in[0];
    const float* W1  = (const float*)d_in[1];
    const float* b1  = (const float*)d_in[2];
    const float* W2  = (const float*)d_in[3];
    const float* b2  = (const float*)d_in[4];
    const float* Wg1 = (const float*)d_in[5];
    const float* bg1 = (const float*)d_in[6];
    const float* Wg2 = (const float*)d_in[7];
    const float* bg2 = (const float*)d_in[8];
    float* out = (float*)d_out;

    cudaFuncSetAttribute(kolmo_v6, cudaFuncAttributeMaxDynamicSharedMemorySize, SM_TOTAL);

    precompute_C<<<DD, 256>>>(W1, b1, W2, Wg1, b2);
    kolmo_v6<<<NCTAS, NTHREADS, SM_TOTAL>>>(x, bg1, Wg2, bg2, out);
}

// round 7
// speedup vs baseline: 5.2148x; 1.3589x over previous
#include <cuda_runtime.h>
#include <cuda_fp16.h>
#include <cstdint>

#define DD 64
#define II 64
#define NBATCH 32768
#define ROWS 128
#define NTHREADS 256
#define NCTAS (NBATCH / ROWS)      // 256
#define C2LOG2E 2.885390081777927f // 2*log2(e)

// ---- smem map (per CTA) ----
#define SM_BB      0       // 64 floats
#define SM_WG2     256     // 64 floats
#define SM_STG     1024    // 2 stages: [B 8192 | wb 512 | pad]
#define STG_STRIDE 9216
#define SM_TOTAL   (1024 + 2 * STG_STRIDE)   // 19456

// ---- device scratch ----
__device__ uint4  g_C4[DD * 512];     // per-d 8KB SW128 fp16 B tile
__device__ float  g_bbp[DD * II];
__device__ float2 g_wb[DD * II];      // prescaled (W1*2log2e, b1*2log2e)

__device__ __forceinline__ uint32_t smem_u32(const void* p) {
    uint32_t a;
    asm("{ .reg .u64 t; cvta.to.shared.u64 t, %1; cvt.u32.u64 %0, t; }" : "=r"(a) : "l"(p));
    return a;
}
__device__ __forceinline__ uint32_t swz128(uint32_t off) { return off ^ ((off >> 3) & 0x70); }
__device__ __forceinline__ float ex2f(float x) {
    float r; asm("ex2.approx.ftz.f32 %0, %1;" : "=f"(r) : "f"(x)); return r;
}
// exact tanh given prescaled arg (v' = 2*log2e*v)
__device__ __forceinline__ float tanh_from_p(float vp) {
    float e = ex2f(vp);
    return __fdividef(e - 1.0f, e + 1.0f);
}
__device__ __forceinline__ void ldsm4(uint32_t* r, uint32_t addr) {
    asm volatile("ldmatrix.sync.aligned.m8n8.x4.shared.b16 {%0,%1,%2,%3}, [%4];"
        : "=r"(r[0]), "=r"(r[1]), "=r"(r[2]), "=r"(r[3]) : "r"(addr));
}
__device__ __forceinline__ void mma_fp16(float* c, const uint32_t* a, uint32_t b0, uint32_t b1) {
    asm volatile("mma.sync.aligned.m16n8k16.row.col.f32.f16.f16.f32 "
        "{%0,%1,%2,%3}, {%4,%5,%6,%7}, {%8,%9}, {%0,%1,%2,%3};"
        : "+f"(c[0]), "+f"(c[1]), "+f"(c[2]), "+f"(c[3])
        : "r"(a[0]), "r"(a[1]), "r"(a[2]), "r"(a[3]), "r"(b0), "r"(b1));
}
__device__ __forceinline__ void cp16(uint32_t saddr, const void* gptr) {
    asm volatile("cp.async.cg.shared.global [%0], [%1], 16;" :: "r"(saddr), "l"(gptr) : "memory");
}
#define CP_COMMIT() asm volatile("cp.async.commit_group;" ::: "memory")
#define CP_WAIT0()  asm volatile("cp.async.wait_group 0;" ::: "memory")

// pack float pair -> fp16x2 (b in high half)
__device__ __forceinline__ uint32_t packh2(float a, float b) {
    uint32_t r;
    asm("cvt.rn.f16x2.f32 %0, %1, %2;" : "=r"(r) : "f"(b), "f"(a));
    return r;
}

// ---------------------------------------------------------------------------
// Kernel A: fold W2[d] @ Wg1 slice -> C[d] fp16 SW128 tiles; bias partials;
// prescaled W1/b1.
// ---------------------------------------------------------------------------
__global__ __launch_bounds__(256) void precompute_C(
    const float* __restrict__ W1, const float* __restrict__ b1,
    const float* __restrict__ W2, const float* __restrict__ Wg1,
    const float* __restrict__ b2)
{
    __shared__ float W2s[II * II];
    __shared__ float Wgs[II * II];
    const int d = blockIdx.x;
    const int tid = threadIdx.x;

    for (int t = tid; t < II * II; t += 256) {
        W2s[t] = W2[d * II * II + t];
        Wgs[t] = Wg1[d * II * II + t];
    }
    __syncthreads();

    __half* Cd = (__half*)(g_C4 + (size_t)d * 512);

    for (int t = tid; t < II * II; t += 256) {
        const int i = t >> 6;     // K index
        const int j = t & 63;     // N index
        float s = 0.0f;
        #pragma unroll 16
        for (int o = 0; o < II; ++o)
            s = fmaf(W2s[i * II + o], Wgs[o * II + j], s);
        Cd[swz128((uint32_t)(j * 128 + i * 2)) >> 1] = __float2half_rn(s);
    }

    if (tid < II) {
        const int j = tid;
        float s = 0.0f;
        #pragma unroll 16
        for (int o = 0; o < II; ++o)
            s = fmaf(b2[d * II + o], Wgs[o * II + j], s);
        g_bbp[d * II + j] = s;
        g_wb[d * II + j] = make_float2(W1[d * II + j] * C2LOG2E,
                                       b1[d * II + j] * C2LOG2E);
    }
}

// ---------------------------------------------------------------------------
// Kernel B: fp16 A in-register (tanh on the fly), single fp16 MMA per tile.
// grid=256, 256 threads (8 warps, M=16 each), 2 CTAs/SM.
// ---------------------------------------------------------------------------
__global__ __launch_bounds__(NTHREADS, 2)
void kolmo_v7(
    const float* __restrict__ x,    // [B, 64]
    const float* __restrict__ bg1,  // [64]
    const float* __restrict__ Wg2,  // [64, 1]
    const float* __restrict__ bg2,  // [1]
    float* __restrict__ out)        // [B, 1]
{
    extern __shared__ char smem[];
    const uint32_t sb = smem_u32(smem);
    const int tid  = threadIdx.x;
    const int wid  = tid >> 5;
    const int lane = tid & 31;
    const int r0   = blockIdx.x * ROWS;

    float* bb_s  = (float*)(smem + SM_BB);
    float* wg2_s = (float*)(smem + SM_WG2);

    if (tid < II) {
        float s = bg1[tid];
        #pragma unroll 16
        for (int d = 0; d < DD; ++d) s += g_bbp[d * II + tid];
        bb_s[tid]  = s;
        wg2_s[tid] = Wg2[tid];
    }

    // issue B stage 0 (C tile + wb) via cp.async
    {
        const uint32_t st = sb + SM_STG;
        cp16(st        + tid * 16, g_C4 + tid);
        cp16(st + 4096 + tid * 16, g_C4 + 256 + tid);
        if (tid < 32) cp16(st + 8192 + tid * 16, (const char*)g_wb + tid * 16);
        CP_COMMIT();
    }

    // lane geometry
    const uint32_t bRow  = (uint32_t)((lane & 7) + ((lane & 16) ? 8 : 0));
    const uint32_t bKadd = (lane & 8) ? 16u : 0u;
    const int  mrow = wid * 16 + (lane >> 2);        // CTA-local row (and +8)
    const int  kc   = 2 * (lane & 3);
    const float* xr0 = x + (size_t)(r0 + mrow) * 64;
    const float* xr1 = x + (size_t)(r0 + mrow + 8) * 64;

    float acc[32];
    #pragma unroll
    for (int i = 0; i < 32; ++i) acc[i] = 0.0f;

    for (int d = 0; d < DD; ++d) {
        CP_WAIT0();
        __syncthreads();
        const int s = d & 1;
        const uint32_t stg = sb + SM_STG + s * STG_STRIDE;

        // issue next stage into the other buffer
        if (d + 1 < DD) {
            const uint32_t st = sb + SM_STG + (1 - s) * STG_STRIDE;
            const uint4* sc = g_C4 + (size_t)(d + 1) * 512;
            cp16(st        + tid * 16, sc + tid);
            cp16(st + 4096 + tid * 16, sc + 256 + tid);
            if (tid < 32) cp16(st + 8192 + tid * 16,
                               (const char*)(g_wb + (size_t)(d + 1) * II) + tid * 16);
            CP_COMMIT();
        }

        const float xv0 = __ldg(xr0 + d);
        const float xv1 = __ldg(xr1 + d);
        const float2* wb_s = (const float2*)(smem + SM_STG + s * STG_STRIDE + 8192);

        #pragma unroll
        for (int ks = 0; ks < 4; ++ks) {
            // B fragments
            uint32_t bh[16];
            const uint32_t kb = (uint32_t)(ks * 32);
            #pragma unroll
            for (int p = 0; p < 4; ++p) {
                const uint32_t v = (bRow + p * 16) * 128 + kb + bKadd;
                ldsm4(bh + p * 4, stg + swz128(v));
            }
            // A fragment: 8 tanh in-lane -> fp16
            const int k0 = ks * 16 + kc;
            const float2 w0 = wb_s[k0],     w1 = wb_s[k0 + 1];
            const float2 w8 = wb_s[k0 + 8], w9 = wb_s[k0 + 9];
            uint32_t ah[4];
            ah[0] = packh2(tanh_from_p(fmaf(xv0, w0.x, w0.y)),
                           tanh_from_p(fmaf(xv0, w1.x, w1.y)));
            ah[1] = packh2(tanh_from_p(fmaf(xv1, w0.x, w0.y)),
                           tanh_from_p(fmaf(xv1, w1.x, w1.y)));
            ah[2] = packh2(tanh_from_p(fmaf(xv0, w8.x, w8.y)),
                           tanh_from_p(fmaf(xv0, w9.x, w9.y)));
            ah[3] = packh2(tanh_from_p(fmaf(xv1, w8.x, w8.y)),
                           tanh_from_p(fmaf(xv1, w9.x, w9.y)));

            #pragma unroll
            for (int j = 0; j < 8; ++j) {
                const int bi = (j >> 1) * 4 + (j & 1) * 2;
                mma_fp16(acc + j * 4, ah, bh[bi], bh[bi + 1]);
            }
        }
    }

    // ---- epilogue: tanh(acc + bb) . Wg2, reduce over lane&3 ----
    {
        const float bg2v = bg2[0];
        float s0 = 0.0f, s1 = 0.0f;
        #pragma unroll
        for (int j = 0; j < 8; ++j) {
            #pragma unroll
            for (int q = 0; q < 2; ++q) {
                const int n = j * 8 + kc + q;
                const float bbv = bb_s[n], wgv = wg2_s[n];
                s0 = fmaf(tanh_from_p((acc[j * 4 + q]     + bbv) * C2LOG2E), wgv, s0);
                s1 = fmaf(tanh_from_p((acc[j * 4 + 2 + q] + bbv) * C2LOG2E), wgv, s1);
            }
        }
        s0 += __shfl_xor_sync(0xFFFFFFFFu, s0, 1);
        s0 += __shfl_xor_sync(0xFFFFFFFFu, s0, 2);
        s1 += __shfl_xor_sync(0xFFFFFFFFu, s1, 1);
        s1 += __shfl_xor_sync(0xFFFFFFFFu, s1, 2);
        if ((lane & 3) == 0) {
            out[r0 + mrow]     = s0 + bg2v;
            out[r0 + mrow + 8] = s1 + bg2v;
        }
    }
}

// ---------------------------------------------------------------------------
extern "C" void kernel_launch(void* const* d_in, const int* in_sizes, int n_in,
                              void* d_out, int out_size) {
    const float* x   = (const float*)d_in[0];
    const float* W1  = (const float*)d_in[1];
    const float* b1  = (const float*)d_in[2];
    const float* W2  = (const float*)d_in[3];
    const float* b2  = (const float*)d_in[4];
    const float* Wg1 = (const float*)d_in[5];
    const float* bg1 = (const float*)d_in[6];
    const float* Wg2 = (const float*)d_in[7];
    const float* bg2 = (const float*)d_in[8];
    float* out = (float*)d_out;

    cudaFuncSetAttribute(kolmo_v7, cudaFuncAttributeMaxDynamicSharedMemorySize, SM_TOTAL);

    precompute_C<<<DD, 256>>>(W1, b1, W2, Wg1, b2);
    kolmo_v7<<<NCTAS, NTHREADS, SM_TOTAL>>>(x, bg1, Wg2, bg2, out);
}

// round 8
// speedup vs baseline: 5.9556x; 1.1421x over previous
#include <cuda_runtime.h>
#include <cuda_fp16.h>
#include <cstdint>

#define DD 64
#define II 64
#define NBATCH 32768
#define ROWS 128
#define NTHREADS 256
#define NCTAS (NBATCH / ROWS)      // 256
#define C2LOG2E 2.885390081777927f // 2*log2(e)

// ---- smem map (per CTA) ----
#define SM_BB      0       // 64 floats
#define SM_WG2     256     // 64 floats
#define SM_STG     1024    // 2 stages: [B 8192 | wb 512 | pad]
#define STG_STRIDE 9216
#define SM_TOTAL   (1024 + 2 * STG_STRIDE)   // 19456

// ---- device scratch ----
__device__ uint4  g_C4[DD * 512];     // per-d 8KB SW128 fp16 B tile
__device__ float  g_bbp[DD * II];
__device__ float2 g_wb[DD * II];      // raw (W1, b1)

__device__ __forceinline__ uint32_t smem_u32(const void* p) {
    uint32_t a;
    asm("{ .reg .u64 t; cvta.to.shared.u64 t, %1; cvt.u32.u64 %0, t; }" : "=r"(a) : "l"(p));
    return a;
}
__device__ __forceinline__ uint32_t swz128(uint32_t off) { return off ^ ((off >> 3) & 0x70); }
__device__ __forceinline__ float ex2f(float x) {
    float r; asm("ex2.approx.ftz.f32 %0, %1;" : "=f"(r) : "f"(x)); return r;
}
// fast HW tanh (1 MUFU), max rel err ~2^-10.7
__device__ __forceinline__ float tanh_approx(float v) {
    float r; asm("tanh.approx.f32 %0, %1;" : "=f"(r) : "f"(v)); return r;
}
// exact tanh given prescaled arg (v' = 2*log2e*v) — epilogue only
__device__ __forceinline__ float tanh_from_p(float vp) {
    float e = ex2f(vp);
    return __fdividef(e - 1.0f, e + 1.0f);
}
__device__ __forceinline__ void ldsm4(uint32_t* r, uint32_t addr) {
    asm volatile("ldmatrix.sync.aligned.m8n8.x4.shared.b16 {%0,%1,%2,%3}, [%4];"
        : "=r"(r[0]), "=r"(r[1]), "=r"(r[2]), "=r"(r[3]) : "r"(addr));
}
__device__ __forceinline__ void mma_fp16(float* c, const uint32_t* a, uint32_t b0, uint32_t b1) {
    asm volatile("mma.sync.aligned.m16n8k16.row.col.f32.f16.f16.f32 "
        "{%0,%1,%2,%3}, {%4,%5,%6,%7}, {%8,%9}, {%0,%1,%2,%3};"
        : "+f"(c[0]), "+f"(c[1]), "+f"(c[2]), "+f"(c[3])
        : "r"(a[0]), "r"(a[1]), "r"(a[2]), "r"(a[3]), "r"(b0), "r"(b1));
}
__device__ __forceinline__ void cp16(uint32_t saddr, const void* gptr) {
    asm volatile("cp.async.cg.shared.global [%0], [%1], 16;" :: "r"(saddr), "l"(gptr) : "memory");
}
#define CP_COMMIT() asm volatile("cp.async.commit_group;" ::: "memory")
#define CP_WAIT0()  asm volatile("cp.async.wait_group 0;" ::: "memory")

// pack float pair -> fp16x2 (b in high half)
__device__ __forceinline__ uint32_t packh2(float a, float b) {
    uint32_t r;
    asm("cvt.rn.f16x2.f32 %0, %1, %2;" : "=r"(r) : "f"(b), "f"(a));
    return r;
}

// ---------------------------------------------------------------------------
// Kernel A: fold W2[d] @ Wg1 slice -> C[d] fp16 SW128 tiles; bias partials;
// raw W1/b1 pairs. 128 blocks: d = bx>>1, j-half = bx&1.
// ---------------------------------------------------------------------------
__global__ __launch_bounds__(256) void precompute_C(
    const float* __restrict__ W1, const float* __restrict__ b1,
    const float* __restrict__ W2, const float* __restrict__ Wg1,
    const float* __restrict__ b2)
{
    __shared__ float W2s[II * II];   // [i][o] full
    __shared__ float Wgs[II * 32];   // [o][j] half
    const int d  = blockIdx.x >> 1;
    const int j0 = (blockIdx.x & 1) * 32;
    const int tid = threadIdx.x;

    for (int t = tid; t < II * II; t += 256)
        W2s[t] = W2[d * II * II + t];
    for (int t = tid; t < II * 32; t += 256) {
        const int o = t >> 5, j = t & 31;
        Wgs[t] = Wg1[d * II * II + o * II + j0 + j];
    }
    __syncthreads();

    __half* Cd = (__half*)(g_C4 + (size_t)d * 512);

    for (int t = tid; t < II * 32; t += 256) {
        const int i = t >> 5;     // K index
        const int j = t & 31;     // N index (local)
        float s = 0.0f;
        #pragma unroll 16
        for (int o = 0; o < II; ++o)
            s = fmaf(W2s[i * II + o], Wgs[o * 32 + j], s);
        Cd[swz128((uint32_t)((j0 + j) * 128 + i * 2)) >> 1] = __float2half_rn(s);
    }

    if (tid < 32) {
        const int j = tid;
        float s = 0.0f;
        #pragma unroll 16
        for (int o = 0; o < II; ++o)
            s = fmaf(b2[d * II + o], Wgs[o * 32 + j], s);
        g_bbp[d * II + j0 + j] = s;
    }
    if ((blockIdx.x & 1) == 0 && tid < II)
        g_wb[d * II + tid] = make_float2(W1[d * II + tid], b1[d * II + tid]);
}

// ---------------------------------------------------------------------------
// Kernel B: fp16 A in-register (tanh.approx on the fly), single fp16 MMA.
// grid=256, 256 threads (8 warps, M=16 each), 2 CTAs/SM.
// ---------------------------------------------------------------------------
__global__ __launch_bounds__(NTHREADS, 2)
void kolmo_v8(
    const float* __restrict__ x,    // [B, 64]
    const float* __restrict__ bg1,  // [64]
    const float* __restrict__ Wg2,  // [64, 1]
    const float* __restrict__ bg2,  // [1]
    float* __restrict__ out)        // [B, 1]
{
    extern __shared__ char smem[];
    const uint32_t sb = smem_u32(smem);
    const int tid  = threadIdx.x;
    const int wid  = tid >> 5;
    const int lane = tid & 31;
    const int r0   = blockIdx.x * ROWS;

    float* bb_s  = (float*)(smem + SM_BB);
    float* wg2_s = (float*)(smem + SM_WG2);

    if (tid < II) {
        float s = bg1[tid];
        #pragma unroll 16
        for (int d = 0; d < DD; ++d) s += g_bbp[d * II + tid];
        bb_s[tid]  = s;
        wg2_s[tid] = Wg2[tid];
    }

    // issue B stage 0 (C tile + wb) via cp.async
    {
        const uint32_t st = sb + SM_STG;
        cp16(st        + tid * 16, g_C4 + tid);
        cp16(st + 4096 + tid * 16, g_C4 + 256 + tid);
        if (tid < 32) cp16(st + 8192 + tid * 16, (const char*)g_wb + tid * 16);
        CP_COMMIT();
    }

    // lane geometry
    const uint32_t bRow  = (uint32_t)((lane & 7) + ((lane & 16) ? 8 : 0));
    const uint32_t bKadd = (lane & 8) ? 16u : 0u;
    const int  mrow = wid * 16 + (lane >> 2);        // CTA-local row (and +8)
    const int  kc   = 2 * (lane & 3);
    const float* xr0 = x + (size_t)(r0 + mrow) * 64;
    const float* xr1 = x + (size_t)(r0 + mrow + 8) * 64;

    float acc[32];
    #pragma unroll
    for (int i = 0; i < 32; ++i) acc[i] = 0.0f;

    for (int d = 0; d < DD; ++d) {
        CP_WAIT0();
        __syncthreads();
        const int s = d & 1;
        const uint32_t stg = sb + SM_STG + s * STG_STRIDE;

        // issue next stage into the other buffer
        if (d + 1 < DD) {
            const uint32_t st = sb + SM_STG + (1 - s) * STG_STRIDE;
            const uint4* sc = g_C4 + (size_t)(d + 1) * 512;
            cp16(st        + tid * 16, sc + tid);
            cp16(st + 4096 + tid * 16, sc + 256 + tid);
            if (tid < 32) cp16(st + 8192 + tid * 16,
                               (const char*)(g_wb + (size_t)(d + 1) * II) + tid * 16);
            CP_COMMIT();
        }

        const float xv0 = __ldg(xr0 + d);
        const float xv1 = __ldg(xr1 + d);
        const float2* wb_s = (const float2*)(smem + SM_STG + s * STG_STRIDE + 8192);

        #pragma unroll
        for (int ks = 0; ks < 4; ++ks) {
            // B fragments
            uint32_t bh[16];
            const uint32_t kb = (uint32_t)(ks * 32);
            #pragma unroll
            for (int p = 0; p < 4; ++p) {
                const uint32_t v = (bRow + p * 16) * 128 + kb + bKadd;
                ldsm4(bh + p * 4, stg + swz128(v));
            }
            // A fragment: 8 tanh.approx in-lane -> fp16
            const int k0 = ks * 16 + kc;
            const float2 w0 = wb_s[k0],     w1 = wb_s[k0 + 1];
            const float2 w8 = wb_s[k0 + 8], w9 = wb_s[k0 + 9];
            uint32_t ah[4];
            ah[0] = packh2(tanh_approx(fmaf(xv0, w0.x, w0.y)),
                           tanh_approx(fmaf(xv0, w1.x, w1.y)));
            ah[1] = packh2(tanh_approx(fmaf(xv1, w0.x, w0.y)),
                           tanh_approx(fmaf(xv1, w1.x, w1.y)));
            ah[2] = packh2(tanh_approx(fmaf(xv0, w8.x, w8.y)),
                           tanh_approx(fmaf(xv0, w9.x, w9.y)));
            ah[3] = packh2(tanh_approx(fmaf(xv1, w8.x, w8.y)),
                           tanh_approx(fmaf(xv1, w9.x, w9.y)));

            #pragma unroll
            for (int j = 0; j < 8; ++j) {
                const int bi = (j >> 1) * 4 + (j & 1) * 2;
                mma_fp16(acc + j * 4, ah, bh[bi], bh[bi + 1]);
            }
        }
    }

    // ---- epilogue: exact tanh(acc + bb) . Wg2, reduce over lane&3 ----
    {
        const float bg2v = bg2[0];
        float s0 = 0.0f, s1 = 0.0f;
        #pragma unroll
        for (int j = 0; j < 8; ++j) {
            #pragma unroll
            for (int q = 0; q < 2; ++q) {
                const int n = j * 8 + kc + q;
                const float bbv = bb_s[n], wgv = wg2_s[n];
                s0 = fmaf(tanh_from_p((acc[j * 4 + q]     + bbv) * C2LOG2E), wgv, s0);
                s1 = fmaf(tanh_from_p((acc[j * 4 + 2 + q] + bbv) * C2LOG2E), wgv, s1);
            }
        }
        s0 += __shfl_xor_sync(0xFFFFFFFFu, s0, 1);
        s0 += __shfl_xor_sync(0xFFFFFFFFu, s0, 2);
        s1 += __shfl_xor_sync(0xFFFFFFFFu, s1, 1);
        s1 += __shfl_xor_sync(0xFFFFFFFFu, s1, 2);
        if ((lane & 3) == 0) {
            out[r0 + mrow]     = s0 + bg2v;
            out[r0 + mrow + 8] = s1 + bg2v;
        }
    }
}

// ---------------------------------------------------------------------------
extern "C" void kernel_launch(void* const* d_in, const int* in_sizes, int n_in,
                              void* d_out, int out_size) {
    const float* x   = (const float*)d_in[0];
    const float* W1  = (const float*)d_in[1];
    const float* b1  = (const float*)d_in[2];
    const float* W2  = (const float*)d_in[3];
    const float* b2  = (const float*)d_in[4];
    const float* Wg1 = (const float*)d_in[5];
    const float* bg1 = (const float*)d_in[6];
    const float* Wg2 = (const float*)d_in[7];
    const float* bg2 = (const float*)d_in[8];
    float* out = (float*)d_out;

    cudaFuncSetAttribute(kolmo_v8, cudaFuncAttributeMaxDynamicSharedMemorySize, SM_TOTAL);

    precompute_C<<<2 * DD, 256>>>(W1, b1, W2, Wg1, b2);
    kolmo_v8<<<NCTAS, NTHREADS, SM_TOTAL>>>(x, bg1, Wg2, bg2, out);
}

// round 9
// speedup vs baseline: 6.1000x; 1.0243x over previous
#include <cuda_runtime.h>
#include <cuda_fp16.h>
#include <cstdint>

#define DD 64
#define II 64
#define NBATCH 32768
#define ROWS 128
#define NTHREADS 256
#define NCTAS (NBATCH / ROWS)      // 256
#define C2LOG2E 2.885390081777927f // 2*log2(e)

// ---- smem map (per CTA) ----
#define SM_BB      0       // 64 floats
#define SM_WG2     256     // 64 floats
#define SM_STG     1024    // 3 stages: [B 8192 | wb 512 | pad]
#define STG_STRIDE 9216
#define SM_TOTAL   (1024 + 3 * STG_STRIDE)   // 28672

// ---- device scratch ----
__device__ uint4  g_C4[DD * 512];     // per-d 8KB SW128 fp16 B tile
__device__ float  g_bbp[DD * II];
__device__ float2 g_wb[DD * II];      // raw (W1, b1)

__device__ __forceinline__ uint32_t smem_u32(const void* p) {
    uint32_t a;
    asm("{ .reg .u64 t; cvta.to.shared.u64 t, %1; cvt.u32.u64 %0, t; }" : "=r"(a) : "l"(p));
    return a;
}
__device__ __forceinline__ uint32_t swz128(uint32_t off) { return off ^ ((off >> 3) & 0x70); }
__device__ __forceinline__ float ex2f(float x) {
    float r; asm("ex2.approx.ftz.f32 %0, %1;" : "=f"(r) : "f"(x)); return r;
}
// exact tanh given prescaled arg (v' = 2*log2e*v) — epilogue only
__device__ __forceinline__ float tanh_from_p(float vp) {
    float e = ex2f(vp);
    return __fdividef(e - 1.0f, e + 1.0f);
}
// packed fp16x2 tanh (1 MUFU for 2 values)
__device__ __forceinline__ uint32_t tanh_h2(uint32_t a) {
    uint32_t r; asm("tanh.approx.f16x2 %0, %1;" : "=r"(r) : "r"(a)); return r;
}
__device__ __forceinline__ void ldsm4(uint32_t* r, uint32_t addr) {
    asm volatile("ldmatrix.sync.aligned.m8n8.x4.shared.b16 {%0,%1,%2,%3}, [%4];"
        : "=r"(r[0]), "=r"(r[1]), "=r"(r[2]), "=r"(r[3]) : "r"(addr));
}
__device__ __forceinline__ void mma_fp16(float* c, const uint32_t* a, uint32_t b0, uint32_t b1) {
    asm volatile("mma.sync.aligned.m16n8k16.row.col.f32.f16.f16.f32 "
        "{%0,%1,%2,%3}, {%4,%5,%6,%7}, {%8,%9}, {%0,%1,%2,%3};"
        : "+f"(c[0]), "+f"(c[1]), "+f"(c[2]), "+f"(c[3])
        : "r"(a[0]), "r"(a[1]), "r"(a[2]), "r"(a[3]), "r"(b0), "r"(b1));
}
__device__ __forceinline__ void cp16(uint32_t saddr, const void* gptr) {
    asm volatile("cp.async.cg.shared.global [%0], [%1], 16;" :: "r"(saddr), "l"(gptr) : "memory");
}
#define CP_COMMIT() asm volatile("cp.async.commit_group;" ::: "memory")
#define CP_WAIT1()  asm volatile("cp.async.wait_group 1;" ::: "memory")

// pack float pair -> fp16x2 (b in high half)
__device__ __forceinline__ uint32_t packh2(float a, float b) {
    uint32_t r;
    asm("cvt.rn.f16x2.f32 %0, %1, %2;" : "=r"(r) : "f"(b), "f"(a));
    return r;
}

// ---------------------------------------------------------------------------
// Kernel A: fold W2[d] @ Wg1 slice -> C[d] fp16 SW128 tiles; bias partials;
// raw W1/b1 pairs. 128 blocks: d = bx>>1, j-half = bx&1.
// ---------------------------------------------------------------------------
__global__ __launch_bounds__(256) void precompute_C(
    const float* __restrict__ W1, const float* __restrict__ b1,
    const float* __restrict__ W2, const float* __restrict__ Wg1,
    const float* __restrict__ b2)
{
    __shared__ float W2s[II * II];   // [i][o] full
    __shared__ float Wgs[II * 32];   // [o][j] half
    const int d  = blockIdx.x >> 1;
    const int j0 = (blockIdx.x & 1) * 32;
    const int tid = threadIdx.x;

    for (int t = tid; t < II * II; t += 256)
        W2s[t] = W2[d * II * II + t];
    for (int t = tid; t < II * 32; t += 256) {
        const int o = t >> 5, j = t & 31;
        Wgs[t] = Wg1[d * II * II + o * II + j0 + j];
    }
    __syncthreads();

    __half* Cd = (__half*)(g_C4 + (size_t)d * 512);

    for (int t = tid; t < II * 32; t += 256) {
        const int i = t >> 5;     // K index
        const int j = t & 31;     // N index (local)
        float s = 0.0f;
        #pragma unroll 16
        for (int o = 0; o < II; ++o)
            s = fmaf(W2s[i * II + o], Wgs[o * 32 + j], s);
        Cd[swz128((uint32_t)((j0 + j) * 128 + i * 2)) >> 1] = __float2half_rn(s);
    }

    if (tid < 32) {
        const int j = tid;
        float s = 0.0f;
        #pragma unroll 16
        for (int o = 0; o < II; ++o)
            s = fmaf(b2[d * II + o], Wgs[o * 32 + j], s);
        g_bbp[d * II + j0 + j] = s;
    }
    if ((blockIdx.x & 1) == 0 && tid < II)
        g_wb[d * II + tid] = make_float2(W1[d * II + tid], b1[d * II + tid]);
}

// ---------------------------------------------------------------------------
// helper: issue one B stage (C tile + wb) via cp.async
// ---------------------------------------------------------------------------
__device__ __forceinline__ void issue_stage(uint32_t sb, int slot, int d, int tid) {
    const uint32_t st = sb + SM_STG + slot * STG_STRIDE;
    const uint4* sc = g_C4 + (size_t)d * 512;
    cp16(st        + tid * 16, sc + tid);
    cp16(st + 4096 + tid * 16, sc + 256 + tid);
    if (tid < 32) cp16(st + 8192 + tid * 16,
                       (const char*)(g_wb + (size_t)d * II) + tid * 16);
}

// ---------------------------------------------------------------------------
// Kernel B: fp16x2 tanh A in-register, single fp16 MMA, 3-stage cp.async ring.
// grid=256, 256 threads (8 warps, M=16 each), 2 CTAs/SM.
// ---------------------------------------------------------------------------
__global__ __launch_bounds__(NTHREADS, 2)
void kolmo_v9(
    const float* __restrict__ x,    // [B, 64]
    const float* __restrict__ bg1,  // [64]
    const float* __restrict__ Wg2,  // [64, 1]
    const float* __restrict__ bg2,  // [1]
    float* __restrict__ out)        // [B, 1]
{
    extern __shared__ char smem[];
    const uint32_t sb = smem_u32(smem);
    const int tid  = threadIdx.x;
    const int wid  = tid >> 5;
    const int lane = tid & 31;
    const int r0   = blockIdx.x * ROWS;

    float* bb_s  = (float*)(smem + SM_BB);
    float* wg2_s = (float*)(smem + SM_WG2);

    if (tid < II) {
        float s = bg1[tid];
        #pragma unroll 16
        for (int d = 0; d < DD; ++d) s += g_bbp[d * II + tid];
        bb_s[tid]  = s;
        wg2_s[tid] = Wg2[tid];
    }

    // prologue: issue stages 0 and 1 (separate commit groups)
    issue_stage(sb, 0, 0, tid); CP_COMMIT();
    issue_stage(sb, 1, 1, tid); CP_COMMIT();

    // lane geometry
    const uint32_t bRow  = (uint32_t)((lane & 7) + ((lane & 16) ? 8 : 0));
    const uint32_t bKadd = (lane & 8) ? 16u : 0u;
    const int  mrow = wid * 16 + (lane >> 2);        // CTA-local row (and +8)
    const int  kc   = 2 * (lane & 3);
    const float* xr0 = x + (size_t)(r0 + mrow) * 64;
    const float* xr1 = x + (size_t)(r0 + mrow + 8) * 64;

    float acc[32];
    #pragma unroll
    for (int i = 0; i < 32; ++i) acc[i] = 0.0f;

    int slot = 0;
    for (int d = 0; d < DD; ++d) {
        // stage d guaranteed complete: its group is 2 commits old
        CP_WAIT1();
        __syncthreads();
        const uint32_t stg = sb + SM_STG + slot * STG_STRIDE;

        // issue stage d+2 into the slot freed by iteration d-1
        if (d + 2 < DD) {
            int ns = slot + 2; if (ns >= 3) ns -= 3;
            issue_stage(sb, ns, d + 2, tid);
        }
        CP_COMMIT();   // (empty group in tail iterations keeps wait semantics)

        const float xv0 = __ldg(xr0 + d);
        const float xv1 = __ldg(xr1 + d);
        const float2* wb_s = (const float2*)(smem + SM_STG + slot * STG_STRIDE + 8192);

        #pragma unroll
        for (int ks = 0; ks < 4; ++ks) {
            // B fragments
            uint32_t bh[16];
            const uint32_t kb = (uint32_t)(ks * 32);
            #pragma unroll
            for (int p = 0; p < 4; ++p) {
                const uint32_t v = (bRow + p * 16) * 128 + kb + bKadd;
                ldsm4(bh + p * 4, stg + swz128(v));
            }
            // A fragment: args fp32 -> fp16x2 -> tanh.approx.f16x2
            const int k0 = ks * 16 + kc;
            const float2 w0 = wb_s[k0],     w1 = wb_s[k0 + 1];
            const float2 w8 = wb_s[k0 + 8], w9 = wb_s[k0 + 9];
            uint32_t ah[4];
            ah[0] = tanh_h2(packh2(fmaf(xv0, w0.x, w0.y), fmaf(xv0, w1.x, w1.y)));
            ah[1] = tanh_h2(packh2(fmaf(xv1, w0.x, w0.y), fmaf(xv1, w1.x, w1.y)));
            ah[2] = tanh_h2(packh2(fmaf(xv0, w8.x, w8.y), fmaf(xv0, w9.x, w9.y)));
            ah[3] = tanh_h2(packh2(fmaf(xv1, w8.x, w8.y), fmaf(xv1, w9.x, w9.y)));

            #pragma unroll
            for (int j = 0; j < 8; ++j) {
                const int bi = (j >> 1) * 4 + (j & 1) * 2;
                mma_fp16(acc + j * 4, ah, bh[bi], bh[bi + 1]);
            }
        }
        if (++slot == 3) slot = 0;
    }

    // ---- epilogue: exact tanh(acc + bb) . Wg2, reduce over lane&3 ----
    {
        const float bg2v = bg2[0];
        float s0 = 0.0f, s1 = 0.0f;
        #pragma unroll
        for (int j = 0; j < 8; ++j) {
            #pragma unroll
            for (int q = 0; q < 2; ++q) {
                const int n = j * 8 + kc + q;
                const float bbv = bb_s[n], wgv = wg2_s[n];
                s0 = fmaf(tanh_from_p((acc[j * 4 + q]     + bbv) * C2LOG2E), wgv, s0);
                s1 = fmaf(tanh_from_p((acc[j * 4 + 2 + q] + bbv) * C2LOG2E), wgv, s1);
            }
        }
        s0 += __shfl_xor_sync(0xFFFFFFFFu, s0, 1);
        s0 += __shfl_xor_sync(0xFFFFFFFFu, s0, 2);
        s1 += __shfl_xor_sync(0xFFFFFFFFu, s1, 1);
        s1 += __shfl_xor_sync(0xFFFFFFFFu, s1, 2);
        if ((lane & 3) == 0) {
            out[r0 + mrow]     = s0 + bg2v;
            out[r0 + mrow + 8] = s1 + bg2v;
        }
    }
}

// ---------------------------------------------------------------------------
extern "C" void kernel_launch(void* const* d_in, const int* in_sizes, int n_in,
                              void* d_out, int out_size) {
    const float* x   = (const float*)d_in[0];
    const float* W1  = (const float*)d_in[1];
    const float* b1  = (const float*)d_in[2];
    const float* W2  = (const float*)d_in[3];
    const float* b2  = (const float*)d_in[4];
    const float* Wg1 = (const float*)d_in[5];
    const float* bg1 = (const float*)d_in[6];
    const float* Wg2 = (const float*)d_in[7];
    const float* bg2 = (const float*)d_in[8];
    float* out = (float*)d_out;

    cudaFuncSetAttribute(kolmo_v9, cudaFuncAttributeMaxDynamicSharedMemorySize, SM_TOTAL);

    precompute_C<<<2 * DD, 256>>>(W1, b1, W2, Wg1, b2);
    kolmo_v9<<<NCTAS, NTHREADS, SM_TOTAL>>>(x, bg1, Wg2, bg2, out);
}

// round 10
// speedup vs baseline: 6.9418x; 1.1380x over previous
#include <cuda_runtime.h>
#include <cuda_fp16.h>
#include <cstdint>

#define DD 64
#define II 64
#define NBATCH 32768
#define ROWS 128
#define NTHREADS 128               // 4 warps, M=32 per warp
#define NCTAS (NBATCH / ROWS)      // 256
#define C2LOG2E 2.885390081777927f // 2*log2(e)

// ---- smem map (per CTA) ----
#define SM_BB      0       // 64 floats
#define SM_WG2     256     // 64 floats
#define SM_STG     1024    // 3 stages: [B 8192 | wb 512 | pad]
#define STG_STRIDE 9216
#define SM_TOTAL   (1024 + 3 * STG_STRIDE)   // 28672

// ---- device scratch ----
__device__ uint4  g_C4[DD * 512];     // per-d 8KB SW128 fp16 B tile
__device__ float  g_bbp[DD * II];
__device__ float2 g_wb[DD * II];      // raw (W1, b1)

__device__ __forceinline__ uint32_t smem_u32(const void* p) {
    uint32_t a;
    asm("{ .reg .u64 t; cvta.to.shared.u64 t, %1; cvt.u32.u64 %0, t; }" : "=r"(a) : "l"(p));
    return a;
}
__device__ __forceinline__ uint32_t swz128(uint32_t off) { return off ^ ((off >> 3) & 0x70); }
__device__ __forceinline__ float ex2f(float x) {
    float r; asm("ex2.approx.ftz.f32 %0, %1;" : "=f"(r) : "f"(x)); return r;
}
// exact tanh given prescaled arg (v' = 2*log2e*v) — epilogue only
__device__ __forceinline__ float tanh_from_p(float vp) {
    float e = ex2f(vp);
    return __fdividef(e - 1.0f, e + 1.0f);
}
// packed fp16x2 tanh (1 MUFU for 2 values)
__device__ __forceinline__ uint32_t tanh_h2(uint32_t a) {
    uint32_t r; asm("tanh.approx.f16x2 %0, %1;" : "=r"(r) : "r"(a)); return r;
}
__device__ __forceinline__ void ldsm4(uint32_t* r, uint32_t addr) {
    asm volatile("ldmatrix.sync.aligned.m8n8.x4.shared.b16 {%0,%1,%2,%3}, [%4];"
        : "=r"(r[0]), "=r"(r[1]), "=r"(r[2]), "=r"(r[3]) : "r"(addr));
}
__device__ __forceinline__ void mma_fp16(float* c, const uint32_t* a, uint32_t b0, uint32_t b1) {
    asm volatile("mma.sync.aligned.m16n8k16.row.col.f32.f16.f16.f32 "
        "{%0,%1,%2,%3}, {%4,%5,%6,%7}, {%8,%9}, {%0,%1,%2,%3};"
        : "+f"(c[0]), "+f"(c[1]), "+f"(c[2]), "+f"(c[3])
        : "r"(a[0]), "r"(a[1]), "r"(a[2]), "r"(a[3]), "r"(b0), "r"(b1));
}
__device__ __forceinline__ void cp16(uint32_t saddr, const void* gptr) {
    asm volatile("cp.async.cg.shared.global [%0], [%1], 16;" :: "r"(saddr), "l"(gptr) : "memory");
}
#define CP_COMMIT() asm volatile("cp.async.commit_group;" ::: "memory")
#define CP_WAIT1()  asm volatile("cp.async.wait_group 1;" ::: "memory")

// pack float pair -> fp16x2 (b in high half)
__device__ __forceinline__ uint32_t packh2(float a, float b) {
    uint32_t r;
    asm("cvt.rn.f16x2.f32 %0, %1, %2;" : "=r"(r) : "f"(b), "f"(a));
    return r;
}

// ---------------------------------------------------------------------------
// Kernel A: fold W2[d] @ Wg1 slice -> C[d] fp16 SW128 tiles; bias partials;
// raw W1/b1 pairs. 128 blocks: d = bx>>1, j-half = bx&1.
// ---------------------------------------------------------------------------
__global__ __launch_bounds__(256) void precompute_C(
    const float* __restrict__ W1, const float* __restrict__ b1,
    const float* __restrict__ W2, const float* __restrict__ Wg1,
    const float* __restrict__ b2)
{
    __shared__ float W2s[II * II];   // [i][o] full
    __shared__ float Wgs[II * 32];   // [o][j] half
    const int d  = blockIdx.x >> 1;
    const int j0 = (blockIdx.x & 1) * 32;
    const int tid = threadIdx.x;

    for (int t = tid; t < II * II; t += 256)
        W2s[t] = W2[d * II * II + t];
    for (int t = tid; t < II * 32; t += 256) {
        const int o = t >> 5, j = t & 31;
        Wgs[t] = Wg1[d * II * II + o * II + j0 + j];
    }
    __syncthreads();

    __half* Cd = (__half*)(g_C4 + (size_t)d * 512);

    for (int t = tid; t < II * 32; t += 256) {
        const int i = t >> 5;     // K index
        const int j = t & 31;     // N index (local)
        float s = 0.0f;
        #pragma unroll 16
        for (int o = 0; o < II; ++o)
            s = fmaf(W2s[i * II + o], Wgs[o * 32 + j], s);
        Cd[swz128((uint32_t)((j0 + j) * 128 + i * 2)) >> 1] = __float2half_rn(s);
    }

    if (tid < 32) {
        const int j = tid;
        float s = 0.0f;
        #pragma unroll 16
        for (int o = 0; o < II; ++o)
            s = fmaf(b2[d * II + o], Wgs[o * 32 + j], s);
        g_bbp[d * II + j0 + j] = s;
    }
    if ((blockIdx.x & 1) == 0 && tid < II)
        g_wb[d * II + tid] = make_float2(W1[d * II + tid], b1[d * II + tid]);
}

// ---------------------------------------------------------------------------
// helper: issue one B stage (C tile + wb) via cp.async (128 threads)
// ---------------------------------------------------------------------------
__device__ __forceinline__ void issue_stage(uint32_t sb, int slot, int d, int tid) {
    const uint32_t st = sb + SM_STG + slot * STG_STRIDE;
    const uint4* sc = g_C4 + (size_t)d * 512;
    #pragma unroll
    for (int k = 0; k < 4; ++k)
        cp16(st + (tid + k * 128) * 16, sc + tid + k * 128);
    if (tid < 32) cp16(st + 8192 + tid * 16,
                       (const char*)(g_wb + (size_t)d * II) + tid * 16);
}

// ---------------------------------------------------------------------------
// Kernel B: M=32/warp, fp16x2 tanh A in-register, single fp16 MMA,
// 3-stage cp.async ring. grid=256, 128 threads (4 warps), 2 CTAs/SM.
// ---------------------------------------------------------------------------
__global__ __launch_bounds__(NTHREADS, 2)
void kolmo_v10(
    const float* __restrict__ x,    // [B, 64]
    const float* __restrict__ bg1,  // [64]
    const float* __restrict__ Wg2,  // [64, 1]
    const float* __restrict__ bg2,  // [1]
    float* __restrict__ out)        // [B, 1]
{
    extern __shared__ char smem[];
    const uint32_t sb = smem_u32(smem);
    const int tid  = threadIdx.x;
    const int wid  = tid >> 5;
    const int lane = tid & 31;
    const int r0   = blockIdx.x * ROWS;

    float* bb_s  = (float*)(smem + SM_BB);
    float* wg2_s = (float*)(smem + SM_WG2);

    if (tid < II) {
        float s = bg1[tid];
        #pragma unroll 16
        for (int d = 0; d < DD; ++d) s += g_bbp[d * II + tid];
        bb_s[tid]  = s;
        wg2_s[tid] = Wg2[tid];
    }

    // prologue: issue stages 0 and 1 (separate commit groups)
    issue_stage(sb, 0, 0, tid); CP_COMMIT();
    issue_stage(sb, 1, 1, tid); CP_COMMIT();

    // lane geometry
    const uint32_t bRow  = (uint32_t)((lane & 7) + ((lane & 16) ? 8 : 0));
    const uint32_t bKadd = (lane & 8) ? 16u : 0u;
    const int  mrow = wid * 32 + (lane >> 2);        // CTA-local row; +8/+16/+24
    const int  kc   = 2 * (lane & 3);
    const float* xr0 = x + (size_t)(r0 + mrow) * 64;
    const float* xr1 = xr0 + 8 * 64;
    const float* xr2 = xr0 + 16 * 64;
    const float* xr3 = xr0 + 24 * 64;

    float acc[64];   // [mtile(2)][j(8)][q(4)]
    #pragma unroll
    for (int i = 0; i < 64; ++i) acc[i] = 0.0f;

    int slot = 0;
    for (int d = 0; d < DD; ++d) {
        CP_WAIT1();
        __syncthreads();
        const uint32_t stg = sb + SM_STG + slot * STG_STRIDE;

        if (d + 2 < DD) {
            int ns = slot + 2; if (ns >= 3) ns -= 3;
            issue_stage(sb, ns, d + 2, tid);
        }
        CP_COMMIT();

        const float xv0 = __ldg(xr0 + d);
        const float xv1 = __ldg(xr1 + d);
        const float xv2 = __ldg(xr2 + d);
        const float xv3 = __ldg(xr3 + d);
        const float2* wb_s = (const float2*)(smem + SM_STG + slot * STG_STRIDE + 8192);

        #pragma unroll
        for (int ks = 0; ks < 4; ++ks) {
            // B fragments (full N=64, this k-slab)
            uint32_t bh[16];
            const uint32_t kb = (uint32_t)(ks * 32);
            #pragma unroll
            for (int p = 0; p < 4; ++p) {
                const uint32_t v = (bRow + p * 16) * 128 + kb + bKadd;
                ldsm4(bh + p * 4, stg + swz128(v));
            }
            // A fragments for both M-tiles: fp32 args -> fp16x2 -> tanh.f16x2
            const int k0 = ks * 16 + kc;
            const float2 w0 = wb_s[k0],     w1 = wb_s[k0 + 1];
            const float2 w8 = wb_s[k0 + 8], w9 = wb_s[k0 + 9];
            uint32_t ah[8];
            ah[0] = tanh_h2(packh2(fmaf(xv0, w0.x, w0.y), fmaf(xv0, w1.x, w1.y)));
            ah[1] = tanh_h2(packh2(fmaf(xv1, w0.x, w0.y), fmaf(xv1, w1.x, w1.y)));
            ah[2] = tanh_h2(packh2(fmaf(xv0, w8.x, w8.y), fmaf(xv0, w9.x, w9.y)));
            ah[3] = tanh_h2(packh2(fmaf(xv1, w8.x, w8.y), fmaf(xv1, w9.x, w9.y)));
            ah[4] = tanh_h2(packh2(fmaf(xv2, w0.x, w0.y), fmaf(xv2, w1.x, w1.y)));
            ah[5] = tanh_h2(packh2(fmaf(xv3, w0.x, w0.y), fmaf(xv3, w1.x, w1.y)));
            ah[6] = tanh_h2(packh2(fmaf(xv2, w8.x, w8.y), fmaf(xv2, w9.x, w9.y)));
            ah[7] = tanh_h2(packh2(fmaf(xv3, w8.x, w8.y), fmaf(xv3, w9.x, w9.y)));

            #pragma unroll
            for (int j = 0; j < 8; ++j) {
                const int bi = (j >> 1) * 4 + (j & 1) * 2;
                mma_fp16(acc +      j * 4, ah,     bh[bi], bh[bi + 1]);
                mma_fp16(acc + 32 + j * 4, ah + 4, bh[bi], bh[bi + 1]);
            }
        }
        if (++slot == 3) slot = 0;
    }

    // ---- epilogue: exact tanh(acc + bb) . Wg2, reduce over lane&3 ----
    {
        const float bg2v = bg2[0];
        float sums[4] = {0.0f, 0.0f, 0.0f, 0.0f};
        #pragma unroll
        for (int t = 0; t < 2; ++t) {
            #pragma unroll
            for (int j = 0; j < 8; ++j) {
                #pragma unroll
                for (int q = 0; q < 2; ++q) {
                    const int n = j * 8 + kc + q;
                    const float bbv = bb_s[n], wgv = wg2_s[n];
                    const float* c = acc + t * 32 + j * 4;
                    sums[t * 2]     = fmaf(tanh_from_p((c[q]     + bbv) * C2LOG2E), wgv, sums[t * 2]);
                    sums[t * 2 + 1] = fmaf(tanh_from_p((c[2 + q] + bbv) * C2LOG2E), wgv, sums[t * 2 + 1]);
                }
            }
        }
        #pragma unroll
        for (int k = 0; k < 4; ++k) {
            sums[k] += __shfl_xor_sync(0xFFFFFFFFu, sums[k], 1);
            sums[k] += __shfl_xor_sync(0xFFFFFFFFu, sums[k], 2);
        }
        if ((lane & 3) == 0) {
            out[r0 + mrow]      = sums[0] + bg2v;
            out[r0 + mrow + 8]  = sums[1] + bg2v;
            out[r0 + mrow + 16] = sums[2] + bg2v;
            out[r0 + mrow + 24] = sums[3] + bg2v;
        }
    }
}

// ---------------------------------------------------------------------------
extern "C" void kernel_launch(void* const* d_in, const int* in_sizes, int n_in,
                              void* d_out, int out_size) {
    const float* x   = (const float*)d_in[0];
    const float* W1  = (const float*)d_in[1];
    const float* b1  = (const float*)d_in[2];
    const float* W2  = (const float*)d_in[3];
    const float* b2  = (const float*)d_in[4];
    const float* Wg1 = (const float*)d_in[5];
    const float* bg1 = (const float*)d_in[6];
    const float* Wg2 = (const float*)d_in[7];
    const float* bg2 = (const float*)d_in[8];
    float* out = (float*)d_out;

    cudaFuncSetAttribute(kolmo_v10, cudaFuncAttributeMaxDynamicSharedMemorySize, SM_TOTAL);

    precompute_C<<<2 * DD, 256>>>(W1, b1, W2, Wg1, b2);
    kolmo_v10<<<NCTAS, NTHREADS, SM_TOTAL>>>(x, bg1, Wg2, bg2, out);
}